// round 6
// baseline (speedup 1.0000x reference)
#include <cuda_runtime.h>
#include <cuda_fp16.h>
#include <math.h>
#include <stdint.h>

#define NQ 4096
#define NK 32768
#define DIN 1024
#define DQK 512
#define DV 512

// ---------------- scratch (no allocations allowed) ----------------
__device__ __half g_X1h[(size_t)NQ * DIN];
__device__ __half g_X1l[(size_t)NQ * DIN];
__device__ __half g_X2h[(size_t)NK * DIN];
__device__ __half g_X2l[(size_t)NK * DIN];
__device__ __half g_Wt[3 * 512 * DIN];    // transposed weights [n][k], fp16 (q|k|v)
__device__ float g_Q[(size_t)NQ * DQK];
__device__ float g_KV[(size_t)NK * 1024]; // row j: K[0..511] | V[512..1023]
__device__ float g_S[NK];                 // per-key score
__device__ int   g_cnt[NQ];
__device__ int   g_off[NQ + 1];
__device__ int   g_cur[NQ];
__device__ int   g_idx[NK];

// ---------------- PTX helpers (portable sm_80+) ----------------
__device__ __forceinline__ void cp16(uint32_t dst, const void* src) {
    asm volatile("cp.async.cg.shared.global [%0], [%1], 16;" :: "r"(dst), "l"(src));
}
__device__ __forceinline__ void cp_commit() {
    asm volatile("cp.async.commit_group;" ::: "memory");
}
template <int N> __device__ __forceinline__ void cp_wait() {
    asm volatile("cp.async.wait_group %0;" :: "n"(N) : "memory");
}
__device__ __forceinline__ void ldsm4(uint32_t* r, uint32_t addr) {
    asm volatile("ldmatrix.sync.aligned.m8n8.x4.shared.b16 {%0,%1,%2,%3}, [%4];"
                 : "=r"(r[0]), "=r"(r[1]), "=r"(r[2]), "=r"(r[3]) : "r"(addr));
}
__device__ __forceinline__ void mma16816(float* c, const uint32_t* a, const uint32_t* b) {
    asm volatile(
        "mma.sync.aligned.m16n8k16.row.col.f32.f16.f16.f32 "
        "{%0,%1,%2,%3}, {%4,%5,%6,%7}, {%8,%9}, {%0,%1,%2,%3};"
        : "+f"(c[0]), "+f"(c[1]), "+f"(c[2]), "+f"(c[3])
        : "r"(a[0]), "r"(a[1]), "r"(a[2]), "r"(a[3]), "r"(b[0]), "r"(b[1]));
}

// ---------------- smem layout (compact 64B rows + chunk swizzle) ----------------
// A tile = 128 rows x 32 fp16 (64B rows), B tile = 256 rows x 32 fp16.
// Chunk (16B) swizzle: c' = c ^ ((row>>1)&3).
#define ATILE_B  8192
#define BTILE_B  16384
#define STAGE_B  (2 * ATILE_B + BTILE_B)   // Ah, Al, B = 32768
#define NSTAGE   4
#define GEMM_SMEM (NSTAGE * STAGE_B)       // 131072

// ---------------- fused 2-term fp16 HMMA GEMM, CTA tile 128x256 ----------------
// C[M, N] = (Ah + Al) * B^T + bias.  A: [M,1024] fp16 hi/lo. B: [N,1024] fp16.
// grid = (N/256, M/128), block = 256 (8 warps, 2x4), warp tile 64x64.
__global__ __launch_bounds__(256, 1)
void gemm2_kernel(const __half* __restrict__ Ah, const __half* __restrict__ Al,
                  const __half* __restrict__ B,
                  const float* __restrict__ bias0, const float* __restrict__ bias1,
                  float* __restrict__ C, int ldc)
{
    extern __shared__ char smem[];
    const uint32_t sb = (uint32_t)__cvta_generic_to_shared(smem);
    const int tid = threadIdx.x, wid = tid >> 5, lane = tid & 31;
    const int warp_m = wid & 1, warp_n = wid >> 1;
    const int m_base = blockIdx.y * 128;
    const int n_base = blockIdx.x * 256;

    float acc[4][8][4];
    #pragma unroll
    for (int i = 0; i < 4; i++)
        #pragma unroll
        for (int j = 0; j < 8; j++)
            #pragma unroll
            for (int k = 0; k < 4; k++) acc[i][j][k] = 0.0f;

    // cp.async fill: per thread 2 A-hi, 2 A-lo, 4 B chunks per stage
    const int fr = tid >> 2, fc = tid & 3;
    const uint32_t fdA0 = (uint32_t)(fr * 64        + ((fc ^ ((fr >> 1) & 3)) << 4));
    const uint32_t fdA1 = (uint32_t)((fr + 64) * 64 + ((fc ^ (((fr + 64) >> 1) & 3)) << 4));

    auto issue_loads = [&](int gi) {
        const int koff = gi * 32, s = gi & 3;
        const uint32_t st = sb + s * STAGE_B;
        const size_t aoff = (size_t)m_base * DIN + koff + fc * 8;
        const size_t boff = (size_t)n_base * DIN + koff + fc * 8;
        cp16(st + fdA0,           Ah + aoff + (size_t)fr * DIN);
        cp16(st + fdA1,           Ah + aoff + (size_t)(fr + 64) * DIN);
        cp16(st + ATILE_B + fdA0, Al + aoff + (size_t)fr * DIN);
        cp16(st + ATILE_B + fdA1, Al + aoff + (size_t)(fr + 64) * DIN);
        const uint32_t sB = st + 2 * ATILE_B;
        #pragma unroll
        for (int rb = 0; rb < 4; rb++) {
            const int r = fr + rb * 64;
            cp16(sB + (uint32_t)(r * 64 + ((fc ^ ((r >> 1) & 3)) << 4)),
                 B + boff + (size_t)r * DIN);
        }
        cp_commit();
    };

    issue_loads(0);
    issue_loads(1);
    issue_loads(2);

    // ldmatrix address components (per-thread constants)
    const int a_row = warp_m * 64 + (lane & 15);                     // + mf*16
    const int a_half = lane >> 4;
    const int a_s = ((lane & 15) >> 1) & 3;
    const int b_row = warp_n * 64 + ((lane >> 4) << 3) + (lane & 7); // + nf2*16
    const int b_half = (lane >> 3) & 1;
    const int b_s = ((lane & 7) >> 1) & 3;

    const int NSTEP = 32;
    for (int gi = 0; gi < NSTEP; gi++) {
        if (gi + 3 < NSTEP) cp_wait<2>(); else cp_wait<0>();
        __syncthreads();
        if (gi + 3 < NSTEP) issue_loads(gi + 3);

        const uint32_t st = sb + (gi & 3) * STAGE_B;
        const uint32_t sAh = st, sAl = st + ATILE_B, sB = st + 2 * ATILE_B;

        #pragma unroll
        for (int kh = 0; kh < 2; kh++) {
            const uint32_t acb = (uint32_t)(((kh * 2 + a_half) ^ a_s) << 4);
            const uint32_t bcb = (uint32_t)(((kh * 2 + b_half) ^ b_s) << 4);
            uint32_t bf[4][4], af[4][4];
            #pragma unroll
            for (int nf2 = 0; nf2 < 4; nf2++)
                ldsm4(bf[nf2], sB + (uint32_t)((b_row + nf2 * 16) * 64) + bcb);
            #pragma unroll
            for (int mf = 0; mf < 4; mf++)
                ldsm4(af[mf], sAh + (uint32_t)((a_row + mf * 16) * 64) + acb);
            #pragma unroll
            for (int mf = 0; mf < 4; mf++)
                #pragma unroll
                for (int nf = 0; nf < 8; nf++)
                    mma16816(acc[mf][nf], af[mf], &bf[nf >> 1][(nf & 1) * 2]);
            #pragma unroll
            for (int mf = 0; mf < 4; mf++)
                ldsm4(af[mf], sAl + (uint32_t)((a_row + mf * 16) * 64) + acb);
            #pragma unroll
            for (int mf = 0; mf < 4; mf++)
                #pragma unroll
                for (int nf = 0; nf < 8; nf++)
                    mma16816(acc[mf][nf], af[mf], &bf[nf >> 1][(nf & 1) * 2]);
        }
    }

    // epilogue: add bias, store fp32 (CTA n-block of 256 stays in one bias half)
    const float* bias = (n_base < 512) ? bias0 : (bias1 - 512);
    const int col0 = n_base + warp_n * 64 + (lane & 3) * 2;
    const int r0   = m_base + warp_m * 64 + (lane >> 2);
    #pragma unroll
    for (int mf = 0; mf < 4; mf++) {
        #pragma unroll
        for (int nf = 0; nf < 8; nf++) {
            const int col = col0 + nf * 8;
            const float b0 = bias[col], b1 = bias[col + 1];
            float* p0 = C + (size_t)(r0 + mf * 16) * ldc + col;
            float* p1 = p0 + 8 * ldc;
            *(float2*)p0 = make_float2(acc[mf][nf][0] + b0, acc[mf][nf][1] + b1);
            *(float2*)p1 = make_float2(acc[mf][nf][2] + b0, acc[mf][nf][3] + b1);
        }
    }
}

// ---------------- fp32 -> fp16 hi/lo split ----------------
__global__ void split_kernel(const float* __restrict__ x,
                             __half* __restrict__ h, __half* __restrict__ l)
{
    const size_t i = 4 * ((size_t)blockIdx.x * 256 + threadIdx.x);
    float4 v = *(const float4*)(x + i);
    __half h0 = __float2half(v.x), h1 = __float2half(v.y);
    __half h2 = __float2half(v.z), h3 = __float2half(v.w);
    __half l0 = __float2half(v.x - __half2float(h0));
    __half l1 = __float2half(v.y - __half2float(h1));
    __half l2 = __float2half(v.z - __half2float(h2));
    __half l3 = __float2half(v.w - __half2float(h3));
    __half2 hp0 = {h0, h1}, hp1 = {h2, h3}, lp0 = {l0, l1}, lp1 = {l2, l3};
    *(__half2*)(h + i)     = hp0;
    *(__half2*)(h + i + 2) = hp1;
    *(__half2*)(l + i)     = lp0;
    *(__half2*)(l + i + 2) = lp1;
}

// ---------------- W[k][n] (1024x512) -> Wt[n][k] fp16, all 3 weights ----------------
__global__ void wtrans_kernel(const float* __restrict__ Wq, const float* __restrict__ Wk,
                              const float* __restrict__ Wv, __half* __restrict__ T)
{
    __shared__ float tile[32][33];
    const float* W = (blockIdx.z == 0) ? Wq : (blockIdx.z == 1) ? Wk : Wv;
    __half* Th = T + (size_t)blockIdx.z * 512 * DIN;
    const int n0 = blockIdx.x * 32, k0 = blockIdx.y * 32;
    const int tx = threadIdx.x, ty = threadIdx.y;
    tile[ty][tx] = W[(size_t)(k0 + ty) * 512 + (n0 + tx)];
    __syncthreads();
    Th[(size_t)(n0 + ty) * DIN + (k0 + tx)] = __float2half(tile[tx][ty]);
}

// ---------------- CSR build ----------------
__global__ void zero_cnt_kernel() {
    const int i = blockIdx.x * 256 + threadIdx.x;
    if (i < NQ) g_cnt[i] = 0;
}
__global__ void hist_kernel(const int* __restrict__ row_map) {
    const int j = blockIdx.x * 256 + threadIdx.x;
    if (j < NK) atomicAdd(&g_cnt[row_map[j]], 1);
}
__global__ void scan_kernel() {
    __shared__ int ssum[1024];
    const int t = threadIdx.x;
    const int4 c = *(const int4*)&g_cnt[4 * t];
    const int s = c.x + c.y + c.z + c.w;
    ssum[t] = s;
    __syncthreads();
    int run = s;
    for (int d = 1; d < 1024; d <<= 1) {
        int v = (t >= d) ? ssum[t - d] : 0;
        __syncthreads();
        ssum[t] += v;
        __syncthreads();
    }
    const int excl = ssum[t] - run;
    g_off[4 * t + 0] = excl;
    g_off[4 * t + 1] = excl + c.x;
    g_off[4 * t + 2] = excl + c.x + c.y;
    g_off[4 * t + 3] = excl + c.x + c.y + c.z;
    g_cur[4 * t + 0] = excl;
    g_cur[4 * t + 1] = excl + c.x;
    g_cur[4 * t + 2] = excl + c.x + c.y;
    g_cur[4 * t + 3] = excl + c.x + c.y + c.z;
    if (t == 1023) g_off[NQ] = ssum[t];
}
__global__ void fill_kernel(const int* __restrict__ row_map) {
    const int j = blockIdx.x * 256 + threadIdx.x;
    if (j < NK) {
        const int pos = atomicAdd(&g_cur[row_map[j]], 1);
        g_idx[pos] = j;
    }
}

// ---------------- scores: warp per key, K = g_KV[j][0..511] ----------------
__global__ void score_kernel(const int* __restrict__ row_map) {
    const int j    = blockIdx.x * 8 + (threadIdx.x >> 5);
    const int lane = threadIdx.x & 31;
    const int qi   = row_map[j];
    const float4* q4 = (const float4*)(g_Q + (size_t)qi * DQK);
    const float4* k4 = (const float4*)(g_KV + (size_t)j * 1024);
    float s = 0.0f;
    #pragma unroll
    for (int t = 0; t < 4; t++) {
        float4 a = q4[lane + 32 * t];
        float4 b = k4[lane + 32 * t];
        s += a.x * b.x + a.y * b.y + a.z * b.z + a.w * b.w;
    }
    #pragma unroll
    for (int off = 16; off > 0; off >>= 1)
        s += __shfl_down_sync(0xFFFFFFFFu, s, off);
    if (lane == 0) g_S[j] = s * 0.044194173824159216f;   // 1/sqrt(512)
}

// ---------------- gather: per-query softmax + weighted V sum ----------------
__global__ void gather_kernel(float* __restrict__ out) {
    const int qi = blockIdx.x;
    const int s = g_off[qi], e = g_off[qi + 1];
    const int c = threadIdx.x;
    float* o = out + (size_t)qi * DV + c * 4;
    if (e == s) {
        *(float4*)o = make_float4(0.f, 0.f, 0.f, 0.f);
        return;
    }
    float m = -1e30f;
    for (int t = s; t < e; t++) m = fmaxf(m, g_S[g_idx[t]]);
    float4 acc = make_float4(0.f, 0.f, 0.f, 0.f);
    float den = 0.0f;
    for (int t = s; t < e; t++) {
        const int j = g_idx[t];
        const float w = expf(g_S[j] - m);
        den += w;
        const float4 v = *(const float4*)(g_KV + (size_t)j * 1024 + 512 + c * 4);
        acc.x += w * v.x; acc.y += w * v.y; acc.z += w * v.z; acc.w += w * v.w;
    }
    const float inv = 1.0f / den;
    *(float4*)o = make_float4(acc.x * inv, acc.y * inv, acc.z * inv, acc.w * inv);
}

// ---------------- launcher ----------------
extern "C" void kernel_launch(void* const* d_in, const int* in_sizes, int n_in,
                              void* d_out, int out_size)
{
    const float* X1 = (const float*)d_in[0];
    const float* X2 = (const float*)d_in[1];
    const float* Wq = (const float*)d_in[2];
    const float* bq = (const float*)d_in[3];
    const float* Wk = (const float*)d_in[4];
    const float* bk = (const float*)d_in[5];
    const float* Wv = (const float*)d_in[6];
    const float* bv = (const float*)d_in[7];
    const int*   row_map = (const int*)d_in[8];
    float* out = (float*)d_out;

    __half *x1h, *x1l, *x2h, *x2l, *wt;
    float *Qp, *KVp;
    cudaGetSymbolAddress((void**)&x1h, g_X1h);
    cudaGetSymbolAddress((void**)&x1l, g_X1l);
    cudaGetSymbolAddress((void**)&x2h, g_X2h);
    cudaGetSymbolAddress((void**)&x2l, g_X2l);
    cudaGetSymbolAddress((void**)&wt, g_Wt);
    cudaGetSymbolAddress((void**)&Qp, g_Q);
    cudaGetSymbolAddress((void**)&KVp, g_KV);

    cudaFuncSetAttribute(gemm2_kernel, cudaFuncAttributeMaxDynamicSharedMemorySize, GEMM_SMEM);

    // prep
    split_kernel<<<(NQ * DIN) / 1024, 256>>>(X1, x1h, x1l);
    split_kernel<<<(NK * DIN) / 1024, 256>>>(X2, x2h, x2l);
    wtrans_kernel<<<dim3(16, 32, 3), dim3(32, 32)>>>(Wq, Wk, Wv, wt);
    zero_cnt_kernel<<<NQ / 256, 256>>>();

    // fp16 2-term projections
    gemm2_kernel<<<dim3(2, NQ / 128), 256, GEMM_SMEM>>>(x1h, x1l, wt, bq, bq, Qp, 512);
    gemm2_kernel<<<dim3(4, NK / 128), 256, GEMM_SMEM>>>(x2h, x2l, wt + (size_t)512 * DIN,
                                                        bk, bv, KVp, 1024);

    // CSR over row_map
    hist_kernel<<<NK / 256, 256>>>(row_map);
    scan_kernel<<<1, 1024>>>();
    fill_kernel<<<NK / 256, 256>>>(row_map);

    // degenerate attention
    score_kernel<<<NK / 8, 256>>>(row_map);
    gather_kernel<<<NQ, 128>>>(out);
}

// round 7
// speedup vs baseline: 2.6287x; 2.6287x over previous
#include <cuda_runtime.h>
#include <cuda_fp16.h>
#include <math.h>
#include <stdint.h>

#define NQ 4096
#define NK 32768
#define DIN 1024
#define DQK 512
#define DV 512

// ---------------- scratch (no allocations allowed) ----------------
__device__ __half g_X1h[(size_t)NQ * DIN];
__device__ __half g_X1l[(size_t)NQ * DIN];
__device__ __half g_Qh[(size_t)NQ * DQK];
__device__ __half g_Ql[(size_t)NQ * DQK];
__device__ __half g_Yh[(size_t)NQ * DIN];
__device__ __half g_Yl[(size_t)NQ * DIN];
__device__ __half g_WqT[(size_t)512 * DIN];  // Wq^T [n][k] fp16
__device__ __half g_WvT[(size_t)512 * DIN];  // Wv^T [n][k] fp16
__device__ __half g_WkF[(size_t)DIN * 512];  // Wk as-is [k][n] fp16 (B for U GEMM)
__device__ float g_Q[(size_t)NQ * DQK];
__device__ float g_U[(size_t)NQ * DIN];      // U = Q @ Wk^T  (16.7MB, L2-resident)
__device__ float g_Y[(size_t)NQ * DIN];      // weighted X2 sums
__device__ float g_c0[NQ];                   // bk . Q[i]
__device__ float g_zb[DIN];                  // zero bias (never written; zero-init)
__device__ float g_S[NK];
__device__ int   g_cnt[NQ];
__device__ int   g_off[NQ + 1];
__device__ int   g_cur[NQ];
__device__ int   g_idx[NK];

// ---------------- PTX helpers (portable sm_80+) ----------------
__device__ __forceinline__ void cp16(uint32_t dst, const void* src) {
    asm volatile("cp.async.cg.shared.global [%0], [%1], 16;" :: "r"(dst), "l"(src));
}
__device__ __forceinline__ void cp_commit() {
    asm volatile("cp.async.commit_group;" ::: "memory");
}
template <int N> __device__ __forceinline__ void cp_wait() {
    asm volatile("cp.async.wait_group %0;" :: "n"(N) : "memory");
}
__device__ __forceinline__ void ldsm4(uint32_t* r, uint32_t addr) {
    asm volatile("ldmatrix.sync.aligned.m8n8.x4.shared.b16 {%0,%1,%2,%3}, [%4];"
                 : "=r"(r[0]), "=r"(r[1]), "=r"(r[2]), "=r"(r[3]) : "r"(addr));
}
__device__ __forceinline__ void mma16816(float* c, const uint32_t* a, const uint32_t* b) {
    asm volatile(
        "mma.sync.aligned.m16n8k16.row.col.f32.f16.f16.f32 "
        "{%0,%1,%2,%3}, {%4,%5,%6,%7}, {%8,%9}, {%0,%1,%2,%3};"
        : "+f"(c[0]), "+f"(c[1]), "+f"(c[2]), "+f"(c[3])
        : "r"(a[0]), "r"(a[1]), "r"(a[2]), "r"(a[3]), "r"(b[0]), "r"(b[1]));
}

// ---------------- smem layout (compact 64B rows + chunk swizzle) ----------------
#define TILE_B   8192
#define STAGE_B  (3 * TILE_B)          // Ah, Al, B = 24576
#define NSTAGE   4
#define GEMM_SMEM (NSTAGE * STAGE_B)   // 98304

// ---------------- fused 2-term fp16 HMMA GEMM (R5-proven config) ----------------
// C[M,N] = (Ah + Al) * B^T + bias.  A: [M,kdim] fp16 hi/lo. B: [N,kdim] fp16.
// grid = (N/128, M/128), block = 256 (8 warps, 2x4), warp tile 64x32, occ 2.
__global__ __launch_bounds__(256, 2)
void gemm2_kernel(const __half* __restrict__ Ah, const __half* __restrict__ Al,
                  const __half* __restrict__ B, const float* __restrict__ bias,
                  float* __restrict__ C, int ldc, int kdim)
{
    extern __shared__ char smem[];
    const uint32_t sb = (uint32_t)__cvta_generic_to_shared(smem);
    const int tid = threadIdx.x, wid = tid >> 5, lane = tid & 31;
    const int warp_m = wid & 1, warp_n = wid >> 1;
    const int m_base = blockIdx.y * 128;
    const int n_base = blockIdx.x * 128;

    float acc[4][4][4];
    #pragma unroll
    for (int i = 0; i < 4; i++)
        #pragma unroll
        for (int j = 0; j < 4; j++)
            #pragma unroll
            for (int k = 0; k < 4; k++) acc[i][j][k] = 0.0f;

    const int fr0 = tid >> 2, fc0 = tid & 3;
    const int fr1 = fr0 + 64;
    const uint32_t fd0 = (uint32_t)(fr0 * 64 + ((fc0 ^ ((fr0 >> 1) & 3)) << 4));
    const uint32_t fd1 = (uint32_t)(fr1 * 64 + ((fc0 ^ ((fr1 >> 1) & 3)) << 4));

    auto issue_loads = [&](int gi) {
        const int koff = gi * 32, s = gi & 3;
        const uint32_t st = sb + s * STAGE_B;
        const size_t aoff = (size_t)m_base * kdim + koff + fc0 * 8;
        const size_t boff = (size_t)n_base * kdim + koff + fc0 * 8;
        cp16(st + fd0,              Ah + aoff + (size_t)fr0 * kdim);
        cp16(st + fd1,              Ah + aoff + (size_t)fr1 * kdim);
        cp16(st + TILE_B + fd0,     Al + aoff + (size_t)fr0 * kdim);
        cp16(st + TILE_B + fd1,     Al + aoff + (size_t)fr1 * kdim);
        cp16(st + 2 * TILE_B + fd0, B + boff + (size_t)fr0 * kdim);
        cp16(st + 2 * TILE_B + fd1, B + boff + (size_t)fr1 * kdim);
        cp_commit();
    };

    issue_loads(0);
    issue_loads(1);
    issue_loads(2);

    const int a_row = warp_m * 64 + (lane & 15);
    const int a_half = lane >> 4;
    const int a_s = ((lane & 15) >> 1) & 3;
    const int b_row = warp_n * 32 + ((lane >> 4) << 3) + (lane & 7);
    const int b_half = (lane >> 3) & 1;
    const int b_s = ((lane & 7) >> 1) & 3;

    const int NSTEP = kdim / 32;
    for (int gi = 0; gi < NSTEP; gi++) {
        if (gi + 3 < NSTEP) cp_wait<2>(); else cp_wait<0>();
        __syncthreads();
        if (gi + 3 < NSTEP) issue_loads(gi + 3);

        const uint32_t st = sb + (gi & 3) * STAGE_B;
        const uint32_t sAh = st, sAl = st + TILE_B, sB = st + 2 * TILE_B;

        #pragma unroll
        for (int kh = 0; kh < 2; kh++) {
            const uint32_t acb = (uint32_t)(((kh * 2 + a_half) ^ a_s) << 4);
            const uint32_t bcb = (uint32_t)(((kh * 2 + b_half) ^ b_s) << 4);
            uint32_t bf[2][4], af[4][4];
            #pragma unroll
            for (int nf2 = 0; nf2 < 2; nf2++)
                ldsm4(bf[nf2], sB + (uint32_t)((b_row + nf2 * 16) * 64) + bcb);
            #pragma unroll
            for (int mf = 0; mf < 4; mf++)
                ldsm4(af[mf], sAh + (uint32_t)((a_row + mf * 16) * 64) + acb);
            #pragma unroll
            for (int mf = 0; mf < 4; mf++)
                #pragma unroll
                for (int nf = 0; nf < 4; nf++)
                    mma16816(acc[mf][nf], af[mf], &bf[nf >> 1][(nf & 1) * 2]);
            #pragma unroll
            for (int mf = 0; mf < 4; mf++)
                ldsm4(af[mf], sAl + (uint32_t)((a_row + mf * 16) * 64) + acb);
            #pragma unroll
            for (int mf = 0; mf < 4; mf++)
                #pragma unroll
                for (int nf = 0; nf < 4; nf++)
                    mma16816(acc[mf][nf], af[mf], &bf[nf >> 1][(nf & 1) * 2]);
        }
    }

    const int col0 = n_base + warp_n * 32 + (lane & 3) * 2;
    const int r0   = m_base + warp_m * 64 + (lane >> 2);
    #pragma unroll
    for (int mf = 0; mf < 4; mf++) {
        #pragma unroll
        for (int nf = 0; nf < 4; nf++) {
            const int col = col0 + nf * 8;
            const float b0 = bias[col], b1 = bias[col + 1];
            float* p0 = C + (size_t)(r0 + mf * 16) * ldc + col;
            float* p1 = p0 + 8 * ldc;
            *(float2*)p0 = make_float2(acc[mf][nf][0] + b0, acc[mf][nf][1] + b1);
            *(float2*)p1 = make_float2(acc[mf][nf][2] + b0, acc[mf][nf][3] + b1);
        }
    }
}

// ---------------- fp32 -> fp16 hi/lo split ----------------
__global__ void split_kernel(const float* __restrict__ x,
                             __half* __restrict__ h, __half* __restrict__ l)
{
    const size_t i = 4 * ((size_t)blockIdx.x * 256 + threadIdx.x);
    float4 v = *(const float4*)(x + i);
    __half h0 = __float2half(v.x), h1 = __float2half(v.y);
    __half h2 = __float2half(v.z), h3 = __float2half(v.w);
    __half l0 = __float2half(v.x - __half2float(h0));
    __half l1 = __float2half(v.y - __half2float(h1));
    __half l2 = __float2half(v.z - __half2float(h2));
    __half l3 = __float2half(v.w - __half2float(h3));
    __half2 hp0 = {h0, h1}, hp1 = {h2, h3}, lp0 = {l0, l1}, lp1 = {l2, l3};
    *(__half2*)(h + i)     = hp0;
    *(__half2*)(h + i + 2) = hp1;
    *(__half2*)(l + i)     = lp0;
    *(__half2*)(l + i + 2) = lp1;
}

// ---------------- W[k][n] (1024x512) -> Wt[n][k] fp16 (Wq, Wv) ----------------
__global__ void wtrans_kernel(const float* __restrict__ Wq, const float* __restrict__ Wv,
                              __half* __restrict__ Tq, __half* __restrict__ Tv)
{
    __shared__ float tile[32][33];
    const float* W = (blockIdx.z == 0) ? Wq : Wv;
    __half* Th = (blockIdx.z == 0) ? Tq : Tv;
    const int n0 = blockIdx.x * 32, k0 = blockIdx.y * 32;
    const int tx = threadIdx.x, ty = threadIdx.y;
    tile[ty][tx] = W[(size_t)(k0 + ty) * 512 + (n0 + tx)];
    __syncthreads();
    Th[(size_t)(n0 + ty) * DIN + (k0 + tx)] = __float2half(tile[tx][ty]);
}

// ---------------- Wk fp32 -> fp16, layout unchanged ----------------
__global__ void conv_kernel(const float* __restrict__ W, __half* __restrict__ T) {
    const size_t i = 4 * ((size_t)blockIdx.x * 256 + threadIdx.x);
    float4 v = *(const float4*)(W + i);
    __half2 p0 = {__float2half(v.x), __float2half(v.y)};
    __half2 p1 = {__float2half(v.z), __float2half(v.w)};
    *(__half2*)(T + i)     = p0;
    *(__half2*)(T + i + 2) = p1;
}

// ---------------- CSR build ----------------
__global__ void zero_cnt_kernel() {
    const int i = blockIdx.x * 256 + threadIdx.x;
    if (i < NQ) g_cnt[i] = 0;
}
__global__ void hist_kernel(const int* __restrict__ row_map) {
    const int j = blockIdx.x * 256 + threadIdx.x;
    if (j < NK) atomicAdd(&g_cnt[row_map[j]], 1);
}
__global__ void scan_kernel() {
    __shared__ int ssum[1024];
    const int t = threadIdx.x;
    const int4 c = *(const int4*)&g_cnt[4 * t];
    const int s = c.x + c.y + c.z + c.w;
    ssum[t] = s;
    __syncthreads();
    int run = s;
    for (int d = 1; d < 1024; d <<= 1) {
        int v = (t >= d) ? ssum[t - d] : 0;
        __syncthreads();
        ssum[t] += v;
        __syncthreads();
    }
    const int excl = ssum[t] - run;
    g_off[4 * t + 0] = excl;
    g_off[4 * t + 1] = excl + c.x;
    g_off[4 * t + 2] = excl + c.x + c.y;
    g_off[4 * t + 3] = excl + c.x + c.y + c.z;
    g_cur[4 * t + 0] = excl;
    g_cur[4 * t + 1] = excl + c.x;
    g_cur[4 * t + 2] = excl + c.x + c.y;
    g_cur[4 * t + 3] = excl + c.x + c.y + c.z;
    if (t == 1023) g_off[NQ] = ssum[t];
}
__global__ void fill_kernel(const int* __restrict__ row_map) {
    const int j = blockIdx.x * 256 + threadIdx.x;
    if (j < NK) {
        const int pos = atomicAdd(&g_cur[row_map[j]], 1);
        g_idx[pos] = j;
    }
}

// ---------------- c0[i] = bk . Q[i] ----------------
__global__ void c0_kernel(const float* __restrict__ bk) {
    const int i    = blockIdx.x * 8 + (threadIdx.x >> 5);
    const int lane = threadIdx.x & 31;
    const float4* q4 = (const float4*)(g_Q + (size_t)i * DQK);
    const float4* b4 = (const float4*)bk;
    float s = 0.0f;
    #pragma unroll
    for (int t = 0; t < 4; t++) {
        float4 a = q4[lane + 32 * t];
        float4 b = b4[lane + 32 * t];
        s += a.x * b.x + a.y * b.y + a.z * b.z + a.w * b.w;
    }
    #pragma unroll
    for (int off = 16; off > 0; off >>= 1)
        s += __shfl_down_sync(0xFFFFFFFFu, s, off);
    if (lane == 0) g_c0[i] = s;
}

// ---------------- scores: warp per key, s_j = (X2[j].U[qi] + c0[qi]) * scale ----------------
__global__ void score_kernel(const int* __restrict__ row_map, const float* __restrict__ X2) {
    const int j    = blockIdx.x * 8 + (threadIdx.x >> 5);
    const int lane = threadIdx.x & 31;
    const int qi   = row_map[j];
    const float4* x4 = (const float4*)(X2 + (size_t)j * DIN);
    const float4* u4 = (const float4*)(g_U + (size_t)qi * DIN);
    float s = 0.0f;
    #pragma unroll
    for (int t = 0; t < 8; t++) {
        float4 a = x4[lane + 32 * t];
        float4 b = u4[lane + 32 * t];
        s += a.x * b.x + a.y * b.y + a.z * b.z + a.w * b.w;
    }
    #pragma unroll
    for (int off = 16; off > 0; off >>= 1)
        s += __shfl_down_sync(0xFFFFFFFFu, s, off);
    if (lane == 0) g_S[j] = (s + g_c0[qi]) * 0.044194173824159216f;   // 1/sqrt(512)
}

// ---------------- Y[i] = sum_j softmax_w_j * X2[j]  (per-segment) ----------------
__global__ void gatherY_kernel(const float* __restrict__ X2) {
    const int qi = blockIdx.x;
    const int s = g_off[qi], e = g_off[qi + 1];
    const int c = threadIdx.x;                     // 256 threads, cols 4c..4c+3
    float* y = g_Y + (size_t)qi * DIN + c * 4;
    if (e == s) {
        *(float4*)y = make_float4(0.f, 0.f, 0.f, 0.f);
        return;
    }
    float m = -1e30f;
    for (int t = s; t < e; t++) m = fmaxf(m, g_S[g_idx[t]]);
    float4 acc = make_float4(0.f, 0.f, 0.f, 0.f);
    float den = 0.0f;
    for (int t = s; t < e; t++) {
        const int j = g_idx[t];
        const float w = expf(g_S[j] - m);
        den += w;
        const float4 v = *(const float4*)(X2 + (size_t)j * DIN + c * 4);
        acc.x += w * v.x; acc.y += w * v.y; acc.z += w * v.z; acc.w += w * v.w;
    }
    const float inv = 1.0f / den;
    *(float4*)y = make_float4(acc.x * inv, acc.y * inv, acc.z * inv, acc.w * inv);
}

// ---------------- zero rows with no keys ----------------
__global__ void fix_kernel(float* __restrict__ out) {
    const int qi = blockIdx.x;
    if (g_cnt[qi] != 0) return;
    float* o = out + (size_t)qi * DV + threadIdx.x * 4;
    *(float4*)o = make_float4(0.f, 0.f, 0.f, 0.f);
}

// ---------------- launcher ----------------
extern "C" void kernel_launch(void* const* d_in, const int* in_sizes, int n_in,
                              void* d_out, int out_size)
{
    const float* X1 = (const float*)d_in[0];
    const float* X2 = (const float*)d_in[1];
    const float* Wq = (const float*)d_in[2];
    const float* bq = (const float*)d_in[3];
    const float* Wk = (const float*)d_in[4];
    const float* bk = (const float*)d_in[5];
    const float* Wv = (const float*)d_in[6];
    const float* bv = (const float*)d_in[7];
    const int*   row_map = (const int*)d_in[8];
    float* out = (float*)d_out;

    __half *x1h, *x1l, *qh, *ql, *yh, *yl, *wqT, *wvT, *wkF;
    float *Qp, *Up, *Yp, *zb;
    cudaGetSymbolAddress((void**)&x1h, g_X1h);
    cudaGetSymbolAddress((void**)&x1l, g_X1l);
    cudaGetSymbolAddress((void**)&qh, g_Qh);
    cudaGetSymbolAddress((void**)&ql, g_Ql);
    cudaGetSymbolAddress((void**)&yh, g_Yh);
    cudaGetSymbolAddress((void**)&yl, g_Yl);
    cudaGetSymbolAddress((void**)&wqT, g_WqT);
    cudaGetSymbolAddress((void**)&wvT, g_WvT);
    cudaGetSymbolAddress((void**)&wkF, g_WkF);
    cudaGetSymbolAddress((void**)&Qp, g_Q);
    cudaGetSymbolAddress((void**)&Up, g_U);
    cudaGetSymbolAddress((void**)&Yp, g_Y);
    cudaGetSymbolAddress((void**)&zb, g_zb);

    cudaFuncSetAttribute(gemm2_kernel, cudaFuncAttributeMaxDynamicSharedMemorySize, GEMM_SMEM);

    // CSR (depends only on row_map)
    zero_cnt_kernel<<<NQ / 256, 256>>>();
    hist_kernel<<<NK / 256, 256>>>(row_map);
    scan_kernel<<<1, 1024>>>();
    fill_kernel<<<NK / 256, 256>>>(row_map);

    // prep
    split_kernel<<<(NQ * DIN) / 1024, 256>>>(X1, x1h, x1l);
    wtrans_kernel<<<dim3(16, 32, 2), dim3(32, 32)>>>(Wq, Wv, wqT, wvT);
    conv_kernel<<<(DIN * 512) / 1024, 256>>>(Wk, wkF);

    // Q = X1 @ Wq + bq     (M=4096, N=512, K=1024)
    gemm2_kernel<<<dim3(4, 32), 256, GEMM_SMEM>>>(x1h, x1l, wqT, bq, Qp, 512, 1024);
    split_kernel<<<(NQ * DQK) / 1024, 256>>>(Qp, qh, ql);
    c0_kernel<<<NQ / 8, 256>>>(bk);

    // U = Q @ Wk^T         (M=4096, N=1024, K=512)
    gemm2_kernel<<<dim3(8, 32), 256, GEMM_SMEM>>>(qh, ql, wkF, zb, Up, 1024, 512);

    // degenerate attention in X2-space
    score_kernel<<<NK / 8, 256>>>(row_map, X2);
    gatherY_kernel<<<NQ, 256>>>(X2);

    // C = Y @ Wv + bv      (M=4096, N=512, K=1024)
    split_kernel<<<(NQ * DIN) / 1024, 256>>>(Yp, yh, yl);
    gemm2_kernel<<<dim3(4, 32), 256, GEMM_SMEM>>>(yh, yl, wvT, bv, out, 512, 1024);
    fix_kernel<<<NQ, 128>>>(out);
}

// round 9
// speedup vs baseline: 2.8281x; 1.0758x over previous
#include <cuda_runtime.h>
#include <cuda_fp16.h>
#include <math.h>
#include <stdint.h>

#define NQ 4096
#define NK 32768
#define DIN 1024
#define DQK 512
#define DV 512

// ---------------- scratch (no allocations allowed) ----------------
__device__ __half g_X1h[(size_t)NQ * DIN];
__device__ __half g_X1l[(size_t)NQ * DIN];
__device__ __half g_Yh[(size_t)NQ * DIN];
__device__ __half g_Yl[(size_t)NQ * DIN];
__device__ __half g_Wkh[(size_t)DIN * 512];   // Wk split hi   [d2][c]
__device__ __half g_Wkl[(size_t)DIN * 512];   // Wk split lo
__device__ __half g_Wqf[(size_t)DIN * 512];   // fl16(Wq)      [d1][c]
__device__ __half g_WvT[(size_t)512 * DIN];   // Wv^T [n][k] fp16
__device__ __half g_Gh[(size_t)DIN * DIN];    // Gt = Wk.Wq^T, fp16, rows [d2][d1]
__device__ float g_U[(size_t)NQ * DIN];       // U = X1.G + bq.Wk^T
__device__ float g_c0[NQ];                    // Q[i].bk
__device__ float g_bqWk[DIN];                 // bq . Wk rows
__device__ float g_wqbk[DIN];                 // Wq rows . bk
__device__ float g_bqbk[1];                   // bq . bk
__device__ float g_zb[DIN];                   // zero bias (never written)
__device__ int   g_cnt[NQ];
__device__ int   g_off[NQ + 1];
__device__ int   g_cur[NQ];
__device__ int   g_idx[NK];

// ---------------- PTX helpers (portable sm_80+) ----------------
__device__ __forceinline__ void cp16(uint32_t dst, const void* src) {
    asm volatile("cp.async.cg.shared.global [%0], [%1], 16;" :: "r"(dst), "l"(src));
}
__device__ __forceinline__ void cp_commit() {
    asm volatile("cp.async.commit_group;" ::: "memory");
}
template <int N> __device__ __forceinline__ void cp_wait() {
    asm volatile("cp.async.wait_group %0;" :: "n"(N) : "memory");
}
__device__ __forceinline__ void ldsm4(uint32_t* r, uint32_t addr) {
    asm volatile("ldmatrix.sync.aligned.m8n8.x4.shared.b16 {%0,%1,%2,%3}, [%4];"
                 : "=r"(r[0]), "=r"(r[1]), "=r"(r[2]), "=r"(r[3]) : "r"(addr));
}
__device__ __forceinline__ void mma16816(float* c, const uint32_t* a, const uint32_t* b) {
    asm volatile(
        "mma.sync.aligned.m16n8k16.row.col.f32.f16.f16.f32 "
        "{%0,%1,%2,%3}, {%4,%5,%6,%7}, {%8,%9}, {%0,%1,%2,%3};"
        : "+f"(c[0]), "+f"(c[1]), "+f"(c[2]), "+f"(c[3])
        : "r"(a[0]), "r"(a[1]), "r"(a[2]), "r"(a[3]), "r"(b[0]), "r"(b[1]));
}

// ---------------- smem layout (compact 64B rows + chunk swizzle) ----------------
#define TILE_B   8192
#define STAGE_B  (3 * TILE_B)
#define NSTAGE   4
#define GEMM_SMEM (NSTAGE * STAGE_B)   // 98304

// ---------------- fused 2-term fp16 HMMA GEMM ----------------
// C = (Ah + Al) * B^T + bias.  Optional: half output (Ch), cnt row mask.
// grid = (N/128, M/128), block 256 (8 warps 2x4), warp tile 64x32, occ 2.
__global__ __launch_bounds__(256, 2)
void gemm2_kernel(const __half* __restrict__ Ah, const __half* __restrict__ Al,
                  const __half* __restrict__ B, const float* __restrict__ bias,
                  float* __restrict__ Cf, __half* __restrict__ Ch,
                  const int* __restrict__ cnt, int ldc, int kdim)
{
    extern __shared__ char smem[];
    const uint32_t sb = (uint32_t)__cvta_generic_to_shared(smem);
    const int tid = threadIdx.x, wid = tid >> 5, lane = tid & 31;
    const int warp_m = wid & 1, warp_n = wid >> 1;
    const int m_base = blockIdx.y * 128;
    const int n_base = blockIdx.x * 128;

    float acc[4][4][4];
    #pragma unroll
    for (int i = 0; i < 4; i++)
        #pragma unroll
        for (int j = 0; j < 4; j++)
            #pragma unroll
            for (int k = 0; k < 4; k++) acc[i][j][k] = 0.0f;

    const int fr0 = tid >> 2, fc0 = tid & 3;
    const int fr1 = fr0 + 64;
    const uint32_t fd0 = (uint32_t)(fr0 * 64 + ((fc0 ^ ((fr0 >> 1) & 3)) << 4));
    const uint32_t fd1 = (uint32_t)(fr1 * 64 + ((fc0 ^ ((fr1 >> 1) & 3)) << 4));

    auto issue_loads = [&](int gi) {
        const int koff = gi * 32, s = gi & 3;
        const uint32_t st = sb + s * STAGE_B;
        const size_t aoff = (size_t)m_base * kdim + koff + fc0 * 8;
        const size_t boff = (size_t)n_base * kdim + koff + fc0 * 8;
        cp16(st + fd0,              Ah + aoff + (size_t)fr0 * kdim);
        cp16(st + fd1,              Ah + aoff + (size_t)fr1 * kdim);
        cp16(st + TILE_B + fd0,     Al + aoff + (size_t)fr0 * kdim);
        cp16(st + TILE_B + fd1,     Al + aoff + (size_t)fr1 * kdim);
        cp16(st + 2 * TILE_B + fd0, B + boff + (size_t)fr0 * kdim);
        cp16(st + 2 * TILE_B + fd1, B + boff + (size_t)fr1 * kdim);
        cp_commit();
    };

    issue_loads(0);
    issue_loads(1);
    issue_loads(2);

    const int a_row = warp_m * 64 + (lane & 15);
    const int a_half = lane >> 4;
    const int a_s = ((lane & 15) >> 1) & 3;
    const int b_row = warp_n * 32 + ((lane >> 4) << 3) + (lane & 7);
    const int b_half = (lane >> 3) & 1;
    const int b_s = ((lane & 7) >> 1) & 3;

    const int NSTEP = kdim / 32;
    for (int gi = 0; gi < NSTEP; gi++) {
        if (gi + 3 < NSTEP) cp_wait<2>(); else cp_wait<0>();
        __syncthreads();
        if (gi + 3 < NSTEP) issue_loads(gi + 3);

        const uint32_t st = sb + (gi & 3) * STAGE_B;
        const uint32_t sAh = st, sAl = st + TILE_B, sB = st + 2 * TILE_B;

        #pragma unroll
        for (int kh = 0; kh < 2; kh++) {
            const uint32_t acb = (uint32_t)(((kh * 2 + a_half) ^ a_s) << 4);
            const uint32_t bcb = (uint32_t)(((kh * 2 + b_half) ^ b_s) << 4);
            uint32_t bf[2][4], af[4][4];
            #pragma unroll
            for (int nf2 = 0; nf2 < 2; nf2++)
                ldsm4(bf[nf2], sB + (uint32_t)((b_row + nf2 * 16) * 64) + bcb);
            #pragma unroll
            for (int mf = 0; mf < 4; mf++)
                ldsm4(af[mf], sAh + (uint32_t)((a_row + mf * 16) * 64) + acb);
            #pragma unroll
            for (int mf = 0; mf < 4; mf++)
                #pragma unroll
                for (int nf = 0; nf < 4; nf++)
                    mma16816(acc[mf][nf], af[mf], &bf[nf >> 1][(nf & 1) * 2]);
            #pragma unroll
            for (int mf = 0; mf < 4; mf++)
                ldsm4(af[mf], sAl + (uint32_t)((a_row + mf * 16) * 64) + acb);
            #pragma unroll
            for (int mf = 0; mf < 4; mf++)
                #pragma unroll
                for (int nf = 0; nf < 4; nf++)
                    mma16816(acc[mf][nf], af[mf], &bf[nf >> 1][(nf & 1) * 2]);
        }
    }

    const int col0 = n_base + warp_n * 32 + (lane & 3) * 2;
    const int r0   = m_base + warp_m * 64 + (lane >> 2);
    #pragma unroll
    for (int mf = 0; mf < 4; mf++) {
        const int ra = r0 + mf * 16, rb = ra + 8;
        const bool za = cnt && (cnt[ra] == 0);
        const bool zbm = cnt && (cnt[rb] == 0);
        #pragma unroll
        for (int nf = 0; nf < 4; nf++) {
            const int col = col0 + nf * 8;
            const float b0 = bias[col], b1 = bias[col + 1];
            float v0 = za ? 0.f : acc[mf][nf][0] + b0;
            float v1 = za ? 0.f : acc[mf][nf][1] + b1;
            float v2 = zbm ? 0.f : acc[mf][nf][2] + b0;
            float v3 = zbm ? 0.f : acc[mf][nf][3] + b1;
            if (Ch) {
                __half2 ha = {__float2half(v0), __float2half(v1)};
                __half2 hb = {__float2half(v2), __float2half(v3)};
                *(__half2*)(Ch + (size_t)ra * ldc + col) = ha;
                *(__half2*)(Ch + (size_t)rb * ldc + col) = hb;
            } else {
                *(float2*)(Cf + (size_t)ra * ldc + col) = make_float2(v0, v1);
                *(float2*)(Cf + (size_t)rb * ldc + col) = make_float2(v2, v3);
            }
        }
    }
}

// ---------------- fp32 -> fp16 hi/lo split (generic, 1024 elems/block) ----------------
__global__ void split_kernel(const float* __restrict__ x,
                             __half* __restrict__ h, __half* __restrict__ l)
{
    const size_t i = 4 * ((size_t)blockIdx.x * 256 + threadIdx.x);
    float4 v = *(const float4*)(x + i);
    __half h0 = __float2half(v.x), h1 = __float2half(v.y);
    __half h2 = __float2half(v.z), h3 = __float2half(v.w);
    __half l0 = __float2half(v.x - __half2float(h0));
    __half l1 = __float2half(v.y - __half2float(h1));
    __half l2 = __float2half(v.z - __half2float(h2));
    __half l3 = __float2half(v.w - __half2float(h3));
    __half2 hp0 = {h0, h1}, hp1 = {h2, h3}, lp0 = {l0, l1}, lp1 = {l2, l3};
    *(__half2*)(h + i)     = hp0;
    *(__half2*)(h + i + 2) = hp1;
    *(__half2*)(l + i)     = lp0;
    *(__half2*)(l + i + 2) = lp1;
}

// ---------------- X1 split + c0[i] = X1[i].wqbk + bqbk (block = one row) -------
__global__ void splitc0_kernel(const float* __restrict__ X1) {
    __shared__ float sred[8];
    const int row = blockIdx.x, t = threadIdx.x;
    const size_t i = (size_t)row * DIN + t * 4;
    float4 v = *(const float4*)(X1 + i);
    __half h0 = __float2half(v.x), h1 = __float2half(v.y);
    __half h2 = __float2half(v.z), h3 = __float2half(v.w);
    __half2 hp0 = {h0, h1}, hp1 = {h2, h3};
    __half2 lp0 = {__float2half(v.x - __half2float(h0)), __float2half(v.y - __half2float(h1))};
    __half2 lp1 = {__float2half(v.z - __half2float(h2)), __float2half(v.w - __half2float(h3))};
    *(__half2*)(g_X1h + i)     = hp0;
    *(__half2*)(g_X1h + i + 2) = hp1;
    *(__half2*)(g_X1l + i)     = lp0;
    *(__half2*)(g_X1l + i + 2) = lp1;
    const float4 w = *(const float4*)(g_wqbk + t * 4);
    float d = v.x * w.x + v.y * w.y + v.z * w.z + v.w * w.w;
    #pragma unroll
    for (int off = 16; off > 0; off >>= 1) d += __shfl_down_sync(0xFFFFFFFFu, d, off);
    if ((t & 31) == 0) sred[t >> 5] = d;
    __syncthreads();
    if (t < 8) {
        float s = sred[t];
        #pragma unroll
        for (int off = 4; off > 0; off >>= 1) s += __shfl_down_sync(0xFFu, s, off);
        if (t == 0) g_c0[row] = s + g_bqbk[0];
    }
}

// ---------------- bias vectors: bqWk, wqbk, bqbk ----------------
__global__ void vecprep_kernel(const float* __restrict__ Wq, const float* __restrict__ Wk,
                               const float* __restrict__ bq, const float* __restrict__ bk)
{
    const int gw = blockIdx.x * 8 + (threadIdx.x >> 5);
    const int lane = threadIdx.x & 31;
    const float* rowp; const float* vecp; float* outp;
    if (gw < DIN)            { rowp = Wk + (size_t)gw * 512;          vecp = bq; outp = g_bqWk + gw; }
    else if (gw < 2 * DIN)   { rowp = Wq + (size_t)(gw - DIN) * 512;  vecp = bk; outp = g_wqbk + (gw - DIN); }
    else if (gw == 2 * DIN)  { rowp = bq;                              vecp = bk; outp = g_bqbk; }
    else return;
    const float4* r4 = (const float4*)rowp;
    const float4* v4 = (const float4*)vecp;
    float d = 0.f;
    #pragma unroll
    for (int it = 0; it < 4; it++) {
        float4 a = r4[lane + 32 * it], b = v4[lane + 32 * it];
        d += a.x * b.x + a.y * b.y + a.z * b.z + a.w * b.w;
    }
    #pragma unroll
    for (int off = 16; off > 0; off >>= 1) d += __shfl_down_sync(0xFFFFFFFFu, d, off);
    if (lane == 0) *outp = d;
}

// ---------------- fl16 conversion (layout unchanged) ----------------
__global__ void conv_kernel(const float* __restrict__ W, __half* __restrict__ T) {
    const size_t i = 4 * ((size_t)blockIdx.x * 256 + threadIdx.x);
    float4 v = *(const float4*)(W + i);
    __half2 p0 = {__float2half(v.x), __float2half(v.y)};
    __half2 p1 = {__float2half(v.z), __float2half(v.w)};
    *(__half2*)(T + i)     = p0;
    *(__half2*)(T + i + 2) = p1;
}

// ---------------- Wv[k][n] -> WvT[n][k] fp16 ----------------
__global__ void wtrans_kernel(const float* __restrict__ W, __half* __restrict__ Th) {
    __shared__ float tile[32][33];
    const int n0 = blockIdx.x * 32, k0 = blockIdx.y * 32;
    const int tx = threadIdx.x, ty = threadIdx.y;
    tile[ty][tx] = W[(size_t)(k0 + ty) * 512 + (n0 + tx)];
    __syncthreads();
    Th[(size_t)(n0 + ty) * DIN + (k0 + tx)] = __float2half(tile[tx][ty]);
}

// ---------------- CSR build ----------------
__global__ void zero_cnt_kernel() {
    const int i = blockIdx.x * 256 + threadIdx.x;
    if (i < NQ) g_cnt[i] = 0;
}
__global__ void hist_kernel(const int* __restrict__ row_map) {
    const int j = blockIdx.x * 256 + threadIdx.x;
    if (j < NK) atomicAdd(&g_cnt[row_map[j]], 1);
}
__global__ void scan_kernel() {
    __shared__ int ssum[1024];
    const int t = threadIdx.x;
    const int4 c = *(const int4*)&g_cnt[4 * t];
    const int s = c.x + c.y + c.z + c.w;
    ssum[t] = s;
    __syncthreads();
    int run = s;
    for (int d = 1; d < 1024; d <<= 1) {
        int v = (t >= d) ? ssum[t - d] : 0;
        __syncthreads();
        ssum[t] += v;
        __syncthreads();
    }
    const int excl = ssum[t] - run;
    g_off[4 * t + 0] = excl;
    g_off[4 * t + 1] = excl + c.x;
    g_off[4 * t + 2] = excl + c.x + c.y;
    g_off[4 * t + 3] = excl + c.x + c.y + c.z;
    g_cur[4 * t + 0] = excl;
    g_cur[4 * t + 1] = excl + c.x;
    g_cur[4 * t + 2] = excl + c.x + c.y;
    g_cur[4 * t + 3] = excl + c.x + c.y + c.z;
    if (t == 1023) g_off[NQ] = ssum[t];
}
__global__ void fill_kernel(const int* __restrict__ row_map) {
    const int j = blockIdx.x * 256 + threadIdx.x;
    if (j < NK) {
        const int pos = atomicAdd(&g_cur[row_map[j]], 1);
        g_idx[pos] = j;
    }
}

// ---------------- fused attention: scores + online softmax + Y (fp16 split) ----
#define CH 64
__global__ void attn_kernel(const float* __restrict__ X2) {
    __shared__ float ssc[CH];
    const int qi = blockIdx.x;
    const int s = g_off[qi], e = g_off[qi + 1];
    const int t = threadIdx.x, wid = t >> 5, lane = t & 31;
    const size_t yo = (size_t)qi * DIN + t * 4;
    if (e == s) {
        *(__half2*)(g_Yh + yo) = __half2{__float2half(0.f), __float2half(0.f)};
        *(__half2*)(g_Yh + yo + 2) = __half2{__float2half(0.f), __float2half(0.f)};
        *(__half2*)(g_Yl + yo) = __half2{__float2half(0.f), __float2half(0.f)};
        *(__half2*)(g_Yl + yo + 2) = __half2{__float2half(0.f), __float2half(0.f)};
        return;
    }
    const float c0 = g_c0[qi];
    const float4* u4 = (const float4*)(g_U + (size_t)qi * DIN);
    float m = -1e30f, den = 0.f;
    float4 acc = make_float4(0.f, 0.f, 0.f, 0.f);

    for (int t0 = s; t0 < e; t0 += CH) {
        const int nt = min(CH, e - t0);
        for (int tt = wid; tt < nt; tt += 8) {
            const int j = g_idx[t0 + tt];
            const float4* x4 = (const float4*)(X2 + (size_t)j * DIN);
            float d = 0.f;
            #pragma unroll
            for (int it = 0; it < 8; it++) {
                float4 a = x4[lane + 32 * it], b = u4[lane + 32 * it];
                d += a.x * b.x + a.y * b.y + a.z * b.z + a.w * b.w;
            }
            #pragma unroll
            for (int off = 16; off > 0; off >>= 1)
                d += __shfl_down_sync(0xFFFFFFFFu, d, off);
            if (lane == 0) ssc[tt] = (d + c0) * 0.044194173824159216f;
        }
        __syncthreads();
        float mc = -1e30f;
        for (int k = 0; k < nt; k++) mc = fmaxf(mc, ssc[k]);
        const float mnew = fmaxf(m, mc);
        const float resc = expf(m - mnew);
        den *= resc;
        acc.x *= resc; acc.y *= resc; acc.z *= resc; acc.w *= resc;
        for (int k = 0; k < nt; k++) {
            const int j = g_idx[t0 + k];
            const float w = expf(ssc[k] - mnew);
            den += w;
            const float4 v = *(const float4*)(X2 + (size_t)j * DIN + t * 4);
            acc.x += w * v.x; acc.y += w * v.y; acc.z += w * v.z; acc.w += w * v.w;
        }
        m = mnew;
        __syncthreads();
    }
    const float inv = 1.0f / den;
    const float y0 = acc.x * inv, y1 = acc.y * inv, y2 = acc.z * inv, y3 = acc.w * inv;
    __half h0 = __float2half(y0), h1 = __float2half(y1);
    __half h2 = __float2half(y2), h3 = __float2half(y3);
    __half2 hp0 = {h0, h1}, hp1 = {h2, h3};
    __half2 lp0 = {__float2half(y0 - __half2float(h0)), __float2half(y1 - __half2float(h1))};
    __half2 lp1 = {__float2half(y2 - __half2float(h2)), __float2half(y3 - __half2float(h3))};
    *(__half2*)(g_Yh + yo)     = hp0;
    *(__half2*)(g_Yh + yo + 2) = hp1;
    *(__half2*)(g_Yl + yo)     = lp0;
    *(__half2*)(g_Yl + yo + 2) = lp1;
}

// ---------------- launcher ----------------
extern "C" void kernel_launch(void* const* d_in, const int* in_sizes, int n_in,
                              void* d_out, int out_size)
{
    const float* X1 = (const float*)d_in[0];
    const float* X2 = (const float*)d_in[1];
    const float* Wq = (const float*)d_in[2];
    const float* bq = (const float*)d_in[3];
    const float* Wk = (const float*)d_in[4];
    const float* bk = (const float*)d_in[5];
    const float* Wv = (const float*)d_in[6];
    const float* bv = (const float*)d_in[7];
    const int*   row_map = (const int*)d_in[8];
    float* out = (float*)d_out;

    __half *x1h, *x1l, *yh, *yl, *wkh, *wkl, *wqf, *wvT, *gh;
    float *Up, *zb;
    int* cntp;
    cudaGetSymbolAddress((void**)&x1h, g_X1h);
    cudaGetSymbolAddress((void**)&x1l, g_X1l);
    cudaGetSymbolAddress((void**)&yh, g_Yh);
    cudaGetSymbolAddress((void**)&yl, g_Yl);
    cudaGetSymbolAddress((void**)&wkh, g_Wkh);
    cudaGetSymbolAddress((void**)&wkl, g_Wkl);
    cudaGetSymbolAddress((void**)&wqf, g_Wqf);
    cudaGetSymbolAddress((void**)&wvT, g_WvT);
    cudaGetSymbolAddress((void**)&gh, g_Gh);
    cudaGetSymbolAddress((void**)&Up, g_U);
    cudaGetSymbolAddress((void**)&zb, g_zb);
    cudaGetSymbolAddress((void**)&cntp, g_cnt);

    cudaFuncSetAttribute(gemm2_kernel, cudaFuncAttributeMaxDynamicSharedMemorySize, GEMM_SMEM);

    // CSR over row_map
    zero_cnt_kernel<<<NQ / 256, 256>>>();
    hist_kernel<<<NK / 256, 256>>>(row_map);
    scan_kernel<<<1, 1024>>>();
    fill_kernel<<<NK / 256, 256>>>(row_map);

    // prep
    vecprep_kernel<<<257, 256>>>(Wq, Wk, bq, bk);
    splitc0_kernel<<<NQ, 256>>>(X1);                       // X1 split + c0
    split_kernel<<<(DIN * 512) / 1024, 256>>>(Wk, wkh, wkl);
    conv_kernel<<<(DIN * 512) / 1024, 256>>>(Wq, wqf);
    wtrans_kernel<<<dim3(16, 32), dim3(32, 32)>>>(Wv, wvT);

    // Gt = Wk . Wq^T  (M=1024, N=1024, K=512) -> fp16
    gemm2_kernel<<<dim3(8, 8), 256, GEMM_SMEM>>>(wkh, wkl, wqf, zb, nullptr, gh, nullptr, DIN, 512);
    // U = X1 . G + bq.Wk^T  (M=4096, N=1024, K=1024)
    gemm2_kernel<<<dim3(8, 32), 256, GEMM_SMEM>>>(x1h, x1l, gh, g_bqWk, Up, nullptr, nullptr, DIN, 1024);

    // fused attention -> Y (fp16 hi/lo)
    attn_kernel<<<NQ, 256>>>(X2);

    // C = Y . Wv + bv, empty rows zeroed  (M=4096, N=512, K=1024)
    gemm2_kernel<<<dim3(4, 32), 256, GEMM_SMEM>>>(yh, yl, wvT, bv, out, nullptr, cntp, 512, 1024);
}

// round 10
// speedup vs baseline: 2.9783x; 1.0531x over previous
#include <cuda_runtime.h>
#include <cuda_fp16.h>
#include <math.h>
#include <stdint.h>

#define NQ 4096
#define NK 32768
#define DIN 1024
#define DQK 512
#define DV 512

// ---------------- scratch (no allocations allowed) ----------------
__device__ __half g_X1h[(size_t)NQ * DIN];
__device__ __half g_X1l[(size_t)NQ * DIN];
__device__ __half g_Yh[(size_t)NQ * DIN];
__device__ __half g_Yl[(size_t)NQ * DIN];
__device__ __half g_Wkh[(size_t)DIN * 512];   // Wk split hi   [d2][c]
__device__ __half g_Wkl[(size_t)DIN * 512];   // Wk split lo
__device__ __half g_Wqf[(size_t)DIN * 512];   // fl16(Wq)      [d1][c]
__device__ __half g_WvT[(size_t)512 * DIN];   // Wv^T [n][k] fp16
__device__ __half g_Gh[(size_t)DIN * DIN];    // Gt = Wk.Wq^T, fp16
__device__ float g_U[(size_t)NQ * DIN];       // U = X1.G + bq.Wk^T
__device__ float g_c0[NQ];                    // Q[i].bk
__device__ float g_bqWk[DIN];
__device__ float g_wqbk[DIN];
__device__ float g_bqbk[1];
__device__ float g_zb[DIN];                   // zero bias (never written)
__device__ int   g_cnt[NQ];
__device__ int   g_off[NQ + 1];
__device__ int   g_cur[NQ];
__device__ int   g_idx[NK];

// ---------------- PTX helpers (portable sm_80+) ----------------
__device__ __forceinline__ void cp16(uint32_t dst, const void* src) {
    asm volatile("cp.async.cg.shared.global [%0], [%1], 16;" :: "r"(dst), "l"(src));
}
__device__ __forceinline__ void cp_commit() {
    asm volatile("cp.async.commit_group;" ::: "memory");
}
template <int N> __device__ __forceinline__ void cp_wait() {
    asm volatile("cp.async.wait_group %0;" :: "n"(N) : "memory");
}
__device__ __forceinline__ void ldsm4(uint32_t* r, uint32_t addr) {
    asm volatile("ldmatrix.sync.aligned.m8n8.x4.shared.b16 {%0,%1,%2,%3}, [%4];"
                 : "=r"(r[0]), "=r"(r[1]), "=r"(r[2]), "=r"(r[3]) : "r"(addr));
}
__device__ __forceinline__ void mma16816(float* c, const uint32_t* a, const uint32_t* b) {
    asm volatile(
        "mma.sync.aligned.m16n8k16.row.col.f32.f16.f16.f32 "
        "{%0,%1,%2,%3}, {%4,%5,%6,%7}, {%8,%9}, {%0,%1,%2,%3};"
        : "+f"(c[0]), "+f"(c[1]), "+f"(c[2]), "+f"(c[3])
        : "r"(a[0]), "r"(a[1]), "r"(a[2]), "r"(a[3]), "r"(b[0]), "r"(b[1]));
}

// ---------------- smem layout (compact 64B rows + chunk swizzle) ----------------
#define TILE_B   8192
#define STAGE_B  (3 * TILE_B)
#define NSTAGE   4
#define GEMM_SMEM (NSTAGE * STAGE_B)   // 98304

// ---------------- fused 2-term fp16 HMMA GEMM ----------------
__global__ __launch_bounds__(256, 2)
void gemm2_kernel(const __half* __restrict__ Ah, const __half* __restrict__ Al,
                  const __half* __restrict__ B, const float* __restrict__ bias,
                  float* __restrict__ Cf, __half* __restrict__ Ch,
                  const int* __restrict__ cnt, int ldc, int kdim)
{
    extern __shared__ char smem[];
    const uint32_t sb = (uint32_t)__cvta_generic_to_shared(smem);
    const int tid = threadIdx.x, wid = tid >> 5, lane = tid & 31;
    const int warp_m = wid & 1, warp_n = wid >> 1;
    const int m_base = blockIdx.y * 128;
    const int n_base = blockIdx.x * 128;

    float acc[4][4][4];
    #pragma unroll
    for (int i = 0; i < 4; i++)
        #pragma unroll
        for (int j = 0; j < 4; j++)
            #pragma unroll
            for (int k = 0; k < 4; k++) acc[i][j][k] = 0.0f;

    const int fr0 = tid >> 2, fc0 = tid & 3;
    const int fr1 = fr0 + 64;
    const uint32_t fd0 = (uint32_t)(fr0 * 64 + ((fc0 ^ ((fr0 >> 1) & 3)) << 4));
    const uint32_t fd1 = (uint32_t)(fr1 * 64 + ((fc0 ^ ((fr1 >> 1) & 3)) << 4));

    auto issue_loads = [&](int gi) {
        const int koff = gi * 32, s = gi & 3;
        const uint32_t st = sb + s * STAGE_B;
        const size_t aoff = (size_t)m_base * kdim + koff + fc0 * 8;
        const size_t boff = (size_t)n_base * kdim + koff + fc0 * 8;
        cp16(st + fd0,              Ah + aoff + (size_t)fr0 * kdim);
        cp16(st + fd1,              Ah + aoff + (size_t)fr1 * kdim);
        cp16(st + TILE_B + fd0,     Al + aoff + (size_t)fr0 * kdim);
        cp16(st + TILE_B + fd1,     Al + aoff + (size_t)fr1 * kdim);
        cp16(st + 2 * TILE_B + fd0, B + boff + (size_t)fr0 * kdim);
        cp16(st + 2 * TILE_B + fd1, B + boff + (size_t)fr1 * kdim);
        cp_commit();
    };

    issue_loads(0);
    issue_loads(1);
    issue_loads(2);

    const int a_row = warp_m * 64 + (lane & 15);
    const int a_half = lane >> 4;
    const int a_s = ((lane & 15) >> 1) & 3;
    const int b_row = warp_n * 32 + ((lane >> 4) << 3) + (lane & 7);
    const int b_half = (lane >> 3) & 1;
    const int b_s = ((lane & 7) >> 1) & 3;

    const int NSTEP = kdim / 32;
    for (int gi = 0; gi < NSTEP; gi++) {
        if (gi + 3 < NSTEP) cp_wait<2>(); else cp_wait<0>();
        __syncthreads();
        if (gi + 3 < NSTEP) issue_loads(gi + 3);

        const uint32_t st = sb + (gi & 3) * STAGE_B;
        const uint32_t sAh = st, sAl = st + TILE_B, sB = st + 2 * TILE_B;

        #pragma unroll
        for (int kh = 0; kh < 2; kh++) {
            const uint32_t acb = (uint32_t)(((kh * 2 + a_half) ^ a_s) << 4);
            const uint32_t bcb = (uint32_t)(((kh * 2 + b_half) ^ b_s) << 4);
            uint32_t bf[2][4], af[4][4];
            #pragma unroll
            for (int nf2 = 0; nf2 < 2; nf2++)
                ldsm4(bf[nf2], sB + (uint32_t)((b_row + nf2 * 16) * 64) + bcb);
            #pragma unroll
            for (int mf = 0; mf < 4; mf++)
                ldsm4(af[mf], sAh + (uint32_t)((a_row + mf * 16) * 64) + acb);
            #pragma unroll
            for (int mf = 0; mf < 4; mf++)
                #pragma unroll
                for (int nf = 0; nf < 4; nf++)
                    mma16816(acc[mf][nf], af[mf], &bf[nf >> 1][(nf & 1) * 2]);
            #pragma unroll
            for (int mf = 0; mf < 4; mf++)
                ldsm4(af[mf], sAl + (uint32_t)((a_row + mf * 16) * 64) + acb);
            #pragma unroll
            for (int mf = 0; mf < 4; mf++)
                #pragma unroll
                for (int nf = 0; nf < 4; nf++)
                    mma16816(acc[mf][nf], af[mf], &bf[nf >> 1][(nf & 1) * 2]);
        }
    }

    const int col0 = n_base + warp_n * 32 + (lane & 3) * 2;
    const int r0   = m_base + warp_m * 64 + (lane >> 2);
    #pragma unroll
    for (int mf = 0; mf < 4; mf++) {
        const int ra = r0 + mf * 16, rb = ra + 8;
        const bool za = cnt && (cnt[ra] == 0);
        const bool zbm = cnt && (cnt[rb] == 0);
        #pragma unroll
        for (int nf = 0; nf < 4; nf++) {
            const int col = col0 + nf * 8;
            const float b0 = bias[col], b1 = bias[col + 1];
            float v0 = za ? 0.f : acc[mf][nf][0] + b0;
            float v1 = za ? 0.f : acc[mf][nf][1] + b1;
            float v2 = zbm ? 0.f : acc[mf][nf][2] + b0;
            float v3 = zbm ? 0.f : acc[mf][nf][3] + b1;
            if (Ch) {
                __half2 ha = {__float2half(v0), __float2half(v1)};
                __half2 hb = {__float2half(v2), __float2half(v3)};
                *(__half2*)(Ch + (size_t)ra * ldc + col) = ha;
                *(__half2*)(Ch + (size_t)rb * ldc + col) = hb;
            } else {
                *(float2*)(Cf + (size_t)ra * ldc + col) = make_float2(v0, v1);
                *(float2*)(Cf + (size_t)rb * ldc + col) = make_float2(v2, v3);
            }
        }
    }
}

// ---------------- fuseA: split-Wk | conv-Wq | wtrans-Wv | zero_cnt | vecprep ----
// grid = 1809 blocks x 256 threads
__global__ void fuseA_kernel(const float* __restrict__ Wq, const float* __restrict__ Wk,
                             const float* __restrict__ Wv, const float* __restrict__ bq,
                             const float* __restrict__ bk)
{
    const int b = blockIdx.x, tid = threadIdx.x;
    if (b < 512) {                       // Wk fp32 -> hi/lo split
        const size_t i = 4 * ((size_t)b * 256 + tid);
        float4 v = *(const float4*)(Wk + i);
        __half h0 = __float2half(v.x), h1 = __float2half(v.y);
        __half h2 = __float2half(v.z), h3 = __float2half(v.w);
        __half2 hp0 = {h0, h1}, hp1 = {h2, h3};
        __half2 lp0 = {__float2half(v.x - __half2float(h0)), __float2half(v.y - __half2float(h1))};
        __half2 lp1 = {__float2half(v.z - __half2float(h2)), __float2half(v.w - __half2float(h3))};
        *(__half2*)(g_Wkh + i)     = hp0;
        *(__half2*)(g_Wkh + i + 2) = hp1;
        *(__half2*)(g_Wkl + i)     = lp0;
        *(__half2*)(g_Wkl + i + 2) = lp1;
    } else if (b < 1024) {               // Wq fp32 -> fp16
        const size_t i = 4 * ((size_t)(b - 512) * 256 + tid);
        float4 v = *(const float4*)(Wq + i);
        __half2 p0 = {__float2half(v.x), __float2half(v.y)};
        __half2 p1 = {__float2half(v.z), __float2half(v.w)};
        *(__half2*)(g_Wqf + i)     = p0;
        *(__half2*)(g_Wqf + i + 2) = p1;
    } else if (b < 1536) {               // Wv[k][n] -> WvT[n][k] fp16 (32x32 tile)
        __shared__ float tile[32][33];
        const int bb = b - 1024;
        const int n0 = (bb & 15) * 32, k0 = (bb >> 4) * 32;
        const int tx = tid & 31, ty0 = tid >> 5;
        #pragma unroll
        for (int i = 0; i < 4; i++) {
            const int ty = ty0 + 8 * i;
            tile[ty][tx] = Wv[(size_t)(k0 + ty) * 512 + (n0 + tx)];
        }
        __syncthreads();
        #pragma unroll
        for (int i = 0; i < 4; i++) {
            const int ty = ty0 + 8 * i;
            g_WvT[(size_t)(n0 + ty) * DIN + (k0 + tx)] = __float2half(tile[tx][ty]);
        }
    } else if (b < 1552) {               // zero g_cnt
        g_cnt[(b - 1536) * 256 + tid] = 0;
    } else {                             // vecprep: bqWk, wqbk, bqbk
        const int gw = (b - 1552) * 8 + (tid >> 5);
        const int lane = tid & 31;
        const float* rowp; const float* vecp; float* outp;
        if (gw < DIN)            { rowp = Wk + (size_t)gw * 512;         vecp = bq; outp = g_bqWk + gw; }
        else if (gw < 2 * DIN)   { rowp = Wq + (size_t)(gw - DIN) * 512; vecp = bk; outp = g_wqbk + (gw - DIN); }
        else if (gw == 2 * DIN)  { rowp = bq;                            vecp = bk; outp = g_bqbk; }
        else return;
        const float4* r4 = (const float4*)rowp;
        const float4* v4 = (const float4*)vecp;
        float d = 0.f;
        #pragma unroll
        for (int it = 0; it < 4; it++) {
            float4 a = r4[lane + 32 * it], bb2 = v4[lane + 32 * it];
            d += a.x * bb2.x + a.y * bb2.y + a.z * bb2.z + a.w * bb2.w;
        }
        #pragma unroll
        for (int off = 16; off > 0; off >>= 1) d += __shfl_down_sync(0xFFFFFFFFu, d, off);
        if (lane == 0) *outp = d;
    }
}

// ---------------- fuseB: hist | X1 split + c0 ----------------
// grid = 128 + 4096 blocks x 256 threads
__global__ void fuseB_kernel(const int* __restrict__ row_map, const float* __restrict__ X1)
{
    const int b = blockIdx.x, t = threadIdx.x;
    if (b < 128) {                       // histogram
        atomicAdd(&g_cnt[row_map[b * 256 + t]], 1);
        return;
    }
    __shared__ float sred[8];
    const int row = b - 128;
    const size_t i = (size_t)row * DIN + t * 4;
    float4 v = *(const float4*)(X1 + i);
    __half h0 = __float2half(v.x), h1 = __float2half(v.y);
    __half h2 = __float2half(v.z), h3 = __float2half(v.w);
    __half2 hp0 = {h0, h1}, hp1 = {h2, h3};
    __half2 lp0 = {__float2half(v.x - __half2float(h0)), __float2half(v.y - __half2float(h1))};
    __half2 lp1 = {__float2half(v.z - __half2float(h2)), __float2half(v.w - __half2float(h3))};
    *(__half2*)(g_X1h + i)     = hp0;
    *(__half2*)(g_X1h + i + 2) = hp1;
    *(__half2*)(g_X1l + i)     = lp0;
    *(__half2*)(g_X1l + i + 2) = lp1;
    const float4 w = *(const float4*)(g_wqbk + t * 4);
    float d = v.x * w.x + v.y * w.y + v.z * w.z + v.w * w.w;
    #pragma unroll
    for (int off = 16; off > 0; off >>= 1) d += __shfl_down_sync(0xFFFFFFFFu, d, off);
    if ((t & 31) == 0) sred[t >> 5] = d;
    __syncthreads();
    if (t < 8) {
        float s = sred[t];
        #pragma unroll
        for (int off = 4; off > 0; off >>= 1) s += __shfl_down_sync(0xFFu, s, off);
        if (t == 0) g_c0[row] = s + g_bqbk[0];
    }
}

// ---------------- scan + fill ----------------
__global__ void scan_kernel() {
    __shared__ int ssum[1024];
    const int t = threadIdx.x;
    const int4 c = *(const int4*)&g_cnt[4 * t];
    const int s = c.x + c.y + c.z + c.w;
    ssum[t] = s;
    __syncthreads();
    int run = s;
    for (int d = 1; d < 1024; d <<= 1) {
        int v = (t >= d) ? ssum[t - d] : 0;
        __syncthreads();
        ssum[t] += v;
        __syncthreads();
    }
    const int excl = ssum[t] - run;
    g_off[4 * t + 0] = excl;
    g_off[4 * t + 1] = excl + c.x;
    g_off[4 * t + 2] = excl + c.x + c.y;
    g_off[4 * t + 3] = excl + c.x + c.y + c.z;
    g_cur[4 * t + 0] = excl;
    g_cur[4 * t + 1] = excl + c.x;
    g_cur[4 * t + 2] = excl + c.x + c.y;
    g_cur[4 * t + 3] = excl + c.x + c.y + c.z;
    if (t == 1023) g_off[NQ] = ssum[t];
}
__global__ void fill_kernel(const int* __restrict__ row_map) {
    const int j = blockIdx.x * 256 + threadIdx.x;
    if (j < NK) {
        const int pos = atomicAdd(&g_cur[row_map[j]], 1);
        g_idx[pos] = j;
    }
}

// ---------------- fused attention: scores + online softmax + Y (fp16 split) ----
#define CH 64
__global__ void attn_kernel(const float* __restrict__ X2) {
    __shared__ float ssc[CH];
    const int qi = blockIdx.x;
    const int s = g_off[qi], e = g_off[qi + 1];
    const int t = threadIdx.x, wid = t >> 5, lane = t & 31;
    const size_t yo = (size_t)qi * DIN + t * 4;
    if (e == s) {
        __half2 z = {__float2half(0.f), __float2half(0.f)};
        *(__half2*)(g_Yh + yo) = z; *(__half2*)(g_Yh + yo + 2) = z;
        *(__half2*)(g_Yl + yo) = z; *(__half2*)(g_Yl + yo + 2) = z;
        return;
    }
    const float c0 = g_c0[qi];
    const float4* u4 = (const float4*)(g_U + (size_t)qi * DIN);
    float m = -1e30f, den = 0.f;
    float4 acc = make_float4(0.f, 0.f, 0.f, 0.f);

    for (int t0 = s; t0 < e; t0 += CH) {
        const int nt = min(CH, e - t0);
        for (int tt = wid; tt < nt; tt += 8) {
            const int j = g_idx[t0 + tt];
            const float4* x4 = (const float4*)(X2 + (size_t)j * DIN);
            float d = 0.f;
            #pragma unroll
            for (int it = 0; it < 8; it++) {
                float4 a = x4[lane + 32 * it], b = u4[lane + 32 * it];
                d += a.x * b.x + a.y * b.y + a.z * b.z + a.w * b.w;
            }
            #pragma unroll
            for (int off = 16; off > 0; off >>= 1)
                d += __shfl_down_sync(0xFFFFFFFFu, d, off);
            if (lane == 0) ssc[tt] = (d + c0) * 0.044194173824159216f;
        }
        __syncthreads();
        float mc = -1e30f;
        for (int k = 0; k < nt; k++) mc = fmaxf(mc, ssc[k]);
        const float mnew = fmaxf(m, mc);
        const float resc = expf(m - mnew);
        den *= resc;
        acc.x *= resc; acc.y *= resc; acc.z *= resc; acc.w *= resc;
        for (int k = 0; k < nt; k++) {
            const int j = g_idx[t0 + k];
            const float w = expf(ssc[k] - mnew);
            den += w;
            const float4 v = *(const float4*)(X2 + (size_t)j * DIN + t * 4);
            acc.x += w * v.x; acc.y += w * v.y; acc.z += w * v.z; acc.w += w * v.w;
        }
        m = mnew;
        __syncthreads();
    }
    const float inv = 1.0f / den;
    const float y0 = acc.x * inv, y1 = acc.y * inv, y2 = acc.z * inv, y3 = acc.w * inv;
    __half h0 = __float2half(y0), h1 = __float2half(y1);
    __half h2 = __float2half(y2), h3 = __float2half(y3);
    __half2 hp0 = {h0, h1}, hp1 = {h2, h3};
    __half2 lp0 = {__float2half(y0 - __half2float(h0)), __float2half(y1 - __half2float(h1))};
    __half2 lp1 = {__float2half(y2 - __half2float(h2)), __float2half(y3 - __half2float(h3))};
    *(__half2*)(g_Yh + yo)     = hp0;
    *(__half2*)(g_Yh + yo + 2) = hp1;
    *(__half2*)(g_Yl + yo)     = lp0;
    *(__half2*)(g_Yl + yo + 2) = lp1;
}

// ---------------- launcher ----------------
extern "C" void kernel_launch(void* const* d_in, const int* in_sizes, int n_in,
                              void* d_out, int out_size)
{
    const float* X1 = (const float*)d_in[0];
    const float* X2 = (const float*)d_in[1];
    const float* Wq = (const float*)d_in[2];
    const float* bq = (const float*)d_in[3];
    const float* Wk = (const float*)d_in[4];
    const float* bk = (const float*)d_in[5];
    const float* Wv = (const float*)d_in[6];
    const float* bv = (const float*)d_in[7];
    const int*   row_map = (const int*)d_in[8];
    float* out = (float*)d_out;

    __half *x1h, *x1l, *yh, *yl, *wkh, *wkl, *wqf, *wvT, *gh;
    float *Up, *zb;
    int* cntp;
    cudaGetSymbolAddress((void**)&x1h, g_X1h);
    cudaGetSymbolAddress((void**)&x1l, g_X1l);
    cudaGetSymbolAddress((void**)&yh, g_Yh);
    cudaGetSymbolAddress((void**)&yl, g_Yl);
    cudaGetSymbolAddress((void**)&wkh, g_Wkh);
    cudaGetSymbolAddress((void**)&wkl, g_Wkl);
    cudaGetSymbolAddress((void**)&wqf, g_Wqf);
    cudaGetSymbolAddress((void**)&wvT, g_WvT);
    cudaGetSymbolAddress((void**)&gh, g_Gh);
    cudaGetSymbolAddress((void**)&Up, g_U);
    cudaGetSymbolAddress((void**)&zb, g_zb);
    cudaGetSymbolAddress((void**)&cntp, g_cnt);

    cudaFuncSetAttribute(gemm2_kernel, cudaFuncAttributeMaxDynamicSharedMemorySize, GEMM_SMEM);

    // 1. all independent prep, one launch
    fuseA_kernel<<<1809, 256>>>(Wq, Wk, Wv, bq, bk);
    // 2. Gt = Wk . Wq^T  (M=1024, N=1024, K=512) -> fp16   (needs fuseA only)
    gemm2_kernel<<<dim3(8, 8), 256, GEMM_SMEM>>>(wkh, wkl, wqf, zb, nullptr, gh, nullptr, DIN, 512);
    // 3. hist + X1 split + c0
    fuseB_kernel<<<4224, 256>>>(row_map, X1);
    // 4-5. CSR
    scan_kernel<<<1, 1024>>>();
    fill_kernel<<<NK / 256, 256>>>(row_map);
    // 6. U = X1 . G + bq.Wk^T  (M=4096, N=1024, K=1024)
    gemm2_kernel<<<dim3(8, 32), 256, GEMM_SMEM>>>(x1h, x1l, gh, g_bqWk, Up, nullptr, nullptr, DIN, 1024);
    // 7. fused attention -> Y (fp16 hi/lo)
    attn_kernel<<<NQ, 256>>>(X2);
    // 8. C = Y . Wv + bv, empty rows zeroed  (M=4096, N=512, K=1024)
    gemm2_kernel<<<dim3(4, 32), 256, GEMM_SMEM>>>(yh, yl, wvT, bv, out, nullptr, cntp, 512, 1024);
}

// round 11
// speedup vs baseline: 3.4862x; 1.1705x over previous
#include <cuda_runtime.h>
#include <cuda_fp16.h>
#include <math.h>
#include <stdint.h>

#define NQ 4096
#define NK 32768
#define DIN 1024
#define DQK 512
#define DV 512

// ---------------- scratch (no allocations allowed) ----------------
__device__ __half g_X1h[(size_t)NQ * DIN];
__device__ __half g_Yh[(size_t)NQ * DIN];
__device__ __half g_Yl[(size_t)NQ * DIN];
__device__ __half g_Wkh[(size_t)DIN * 512];   // Wk split hi   [d2][c]
__device__ __half g_Wkl[(size_t)DIN * 512];   // Wk split lo
__device__ __half g_Wqf[(size_t)DIN * 512];   // fl16(Wq)      [d1][c]
__device__ __half g_WvT[(size_t)512 * DIN];   // Wv^T [n][k] fp16
__device__ __half g_Gh[(size_t)DIN * DIN];    // Gt = Wk.Wq^T, fp16
__device__ float g_U[(size_t)NQ * DIN];       // U = X1.G + bq.Wk^T
__device__ float g_c0[NQ];                    // Q[i].bk
__device__ float g_bqWk[DIN];
__device__ float g_wqbk[DIN];
__device__ float g_bqbk[1];
__device__ float g_zb[DIN];                   // zero bias (never written)
__device__ int   g_cnt[NQ];
__device__ int   g_off[NQ + 1];
__device__ int   g_cur[NQ];
__device__ int   g_idx[NK];

// ---------------- PTX helpers (portable sm_80+) ----------------
__device__ __forceinline__ void cp16(uint32_t dst, const void* src) {
    asm volatile("cp.async.cg.shared.global [%0], [%1], 16;" :: "r"(dst), "l"(src));
}
__device__ __forceinline__ void cp_commit() {
    asm volatile("cp.async.commit_group;" ::: "memory");
}
template <int N> __device__ __forceinline__ void cp_wait() {
    asm volatile("cp.async.wait_group %0;" :: "n"(N) : "memory");
}
__device__ __forceinline__ void ldsm4(uint32_t* r, uint32_t addr) {
    asm volatile("ldmatrix.sync.aligned.m8n8.x4.shared.b16 {%0,%1,%2,%3}, [%4];"
                 : "=r"(r[0]), "=r"(r[1]), "=r"(r[2]), "=r"(r[3]) : "r"(addr));
}
__device__ __forceinline__ void mma16816(float* c, const uint32_t* a, const uint32_t* b) {
    asm volatile(
        "mma.sync.aligned.m16n8k16.row.col.f32.f16.f16.f32 "
        "{%0,%1,%2,%3}, {%4,%5,%6,%7}, {%8,%9}, {%0,%1,%2,%3};"
        : "+f"(c[0]), "+f"(c[1]), "+f"(c[2]), "+f"(c[3])
        : "r"(a[0]), "r"(a[1]), "r"(a[2]), "r"(a[3]), "r"(b[0]), "r"(b[1]));
}

#define TILE_B   8192
#define STAGE_B  (3 * TILE_B)
#define NSTAGE   4
#define GEMM_SMEM (NSTAGE * STAGE_B)   // 98304

// ---------------- GEMM body: C = (Ah [+ Al]) * B^T + bias ----------------
template <bool TWO>
__device__ __forceinline__ void gemm_body(
    int bx, int by,
    const __half* __restrict__ Ah, const __half* __restrict__ Al,
    const __half* __restrict__ B, const float* __restrict__ bias,
    float* __restrict__ Cf, __half* __restrict__ Ch,
    const int* __restrict__ cnt, int ldc, int kdim)
{
    extern __shared__ char smem[];
    const uint32_t sb = (uint32_t)__cvta_generic_to_shared(smem);
    const int tid = threadIdx.x, wid = tid >> 5, lane = tid & 31;
    const int warp_m = wid & 1, warp_n = wid >> 1;
    const int m_base = by * 128;
    const int n_base = bx * 128;

    float acc[4][4][4];
    #pragma unroll
    for (int i = 0; i < 4; i++)
        #pragma unroll
        for (int j = 0; j < 4; j++)
            #pragma unroll
            for (int k = 0; k < 4; k++) acc[i][j][k] = 0.0f;

    const int fr0 = tid >> 2, fc0 = tid & 3;
    const int fr1 = fr0 + 64;
    const uint32_t fd0 = (uint32_t)(fr0 * 64 + ((fc0 ^ ((fr0 >> 1) & 3)) << 4));
    const uint32_t fd1 = (uint32_t)(fr1 * 64 + ((fc0 ^ ((fr1 >> 1) & 3)) << 4));

    auto issue_loads = [&](int gi) {
        const int koff = gi * 32, s = gi & 3;
        const uint32_t st = sb + s * STAGE_B;
        const size_t aoff = (size_t)m_base * kdim + koff + fc0 * 8;
        const size_t boff = (size_t)n_base * kdim + koff + fc0 * 8;
        cp16(st + fd0,              Ah + aoff + (size_t)fr0 * kdim);
        cp16(st + fd1,              Ah + aoff + (size_t)fr1 * kdim);
        if (TWO) {
            cp16(st + TILE_B + fd0, Al + aoff + (size_t)fr0 * kdim);
            cp16(st + TILE_B + fd1, Al + aoff + (size_t)fr1 * kdim);
        }
        cp16(st + 2 * TILE_B + fd0, B + boff + (size_t)fr0 * kdim);
        cp16(st + 2 * TILE_B + fd1, B + boff + (size_t)fr1 * kdim);
        cp_commit();
    };

    issue_loads(0);
    issue_loads(1);
    issue_loads(2);

    const int a_row = warp_m * 64 + (lane & 15);
    const int a_half = lane >> 4;
    const int a_s = ((lane & 15) >> 1) & 3;
    const int b_row = warp_n * 32 + ((lane >> 4) << 3) + (lane & 7);
    const int b_half = (lane >> 3) & 1;
    const int b_s = ((lane & 7) >> 1) & 3;

    const int NSTEP = kdim / 32;
    for (int gi = 0; gi < NSTEP; gi++) {
        if (gi + 3 < NSTEP) cp_wait<2>(); else cp_wait<0>();
        __syncthreads();
        if (gi + 3 < NSTEP) issue_loads(gi + 3);

        const uint32_t st = sb + (gi & 3) * STAGE_B;
        const uint32_t sAh = st, sAl = st + TILE_B, sB = st + 2 * TILE_B;

        #pragma unroll
        for (int kh = 0; kh < 2; kh++) {
            const uint32_t acb = (uint32_t)(((kh * 2 + a_half) ^ a_s) << 4);
            const uint32_t bcb = (uint32_t)(((kh * 2 + b_half) ^ b_s) << 4);
            uint32_t bf[2][4], af[4][4];
            #pragma unroll
            for (int nf2 = 0; nf2 < 2; nf2++)
                ldsm4(bf[nf2], sB + (uint32_t)((b_row + nf2 * 16) * 64) + bcb);
            #pragma unroll
            for (int mf = 0; mf < 4; mf++)
                ldsm4(af[mf], sAh + (uint32_t)((a_row + mf * 16) * 64) + acb);
            #pragma unroll
            for (int mf = 0; mf < 4; mf++)
                #pragma unroll
                for (int nf = 0; nf < 4; nf++)
                    mma16816(acc[mf][nf], af[mf], &bf[nf >> 1][(nf & 1) * 2]);
            if (TWO) {
                #pragma unroll
                for (int mf = 0; mf < 4; mf++)
                    ldsm4(af[mf], sAl + (uint32_t)((a_row + mf * 16) * 64) + acb);
                #pragma unroll
                for (int mf = 0; mf < 4; mf++)
                    #pragma unroll
                    for (int nf = 0; nf < 4; nf++)
                        mma16816(acc[mf][nf], af[mf], &bf[nf >> 1][(nf & 1) * 2]);
            }
        }
    }

    const int col0 = n_base + warp_n * 32 + (lane & 3) * 2;
    const int r0   = m_base + warp_m * 64 + (lane >> 2);
    #pragma unroll
    for (int mf = 0; mf < 4; mf++) {
        const int ra = r0 + mf * 16, rb = ra + 8;
        const bool za = cnt && (cnt[ra] == 0);
        const bool zbm = cnt && (cnt[rb] == 0);
        #pragma unroll
        for (int nf = 0; nf < 4; nf++) {
            const int col = col0 + nf * 8;
            const float b0 = bias[col], b1 = bias[col + 1];
            float v0 = za ? 0.f : acc[mf][nf][0] + b0;
            float v1 = za ? 0.f : acc[mf][nf][1] + b1;
            float v2 = zbm ? 0.f : acc[mf][nf][2] + b0;
            float v3 = zbm ? 0.f : acc[mf][nf][3] + b1;
            if (Ch) {
                __half2 ha = {__float2half(v0), __float2half(v1)};
                __half2 hb = {__float2half(v2), __float2half(v3)};
                *(__half2*)(Ch + (size_t)ra * ldc + col) = ha;
                *(__half2*)(Ch + (size_t)rb * ldc + col) = hb;
            } else {
                *(float2*)(Cf + (size_t)ra * ldc + col) = make_float2(v0, v1);
                *(float2*)(Cf + (size_t)rb * ldc + col) = make_float2(v2, v3);
            }
        }
    }
}

// ---------------- fuseA: split-Wk | conv-Wq | wtrans-Wv | zero_cnt | vecprep ----
__global__ void fuseA_kernel(const float* __restrict__ Wq, const float* __restrict__ Wk,
                             const float* __restrict__ Wv, const float* __restrict__ bq,
                             const float* __restrict__ bk)
{
    const int b = blockIdx.x, tid = threadIdx.x;
    if (b < 512) {                       // Wk fp32 -> hi/lo split
        const size_t i = 4 * ((size_t)b * 256 + tid);
        float4 v = *(const float4*)(Wk + i);
        __half h0 = __float2half(v.x), h1 = __float2half(v.y);
        __half h2 = __float2half(v.z), h3 = __float2half(v.w);
        __half2 hp0 = {h0, h1}, hp1 = {h2, h3};
        __half2 lp0 = {__float2half(v.x - __half2float(h0)), __float2half(v.y - __half2float(h1))};
        __half2 lp1 = {__float2half(v.z - __half2float(h2)), __float2half(v.w - __half2float(h3))};
        *(__half2*)(g_Wkh + i)     = hp0;
        *(__half2*)(g_Wkh + i + 2) = hp1;
        *(__half2*)(g_Wkl + i)     = lp0;
        *(__half2*)(g_Wkl + i + 2) = lp1;
    } else if (b < 1024) {               // Wq fp32 -> fp16
        const size_t i = 4 * ((size_t)(b - 512) * 256 + tid);
        float4 v = *(const float4*)(Wq + i);
        __half2 p0 = {__float2half(v.x), __float2half(v.y)};
        __half2 p1 = {__float2half(v.z), __float2half(v.w)};
        *(__half2*)(g_Wqf + i)     = p0;
        *(__half2*)(g_Wqf + i + 2) = p1;
    } else if (b < 1536) {               // Wv[k][n] -> WvT[n][k] fp16
        __shared__ float tile[32][33];
        const int bb = b - 1024;
        const int n0 = (bb & 15) * 32, k0 = (bb >> 4) * 32;
        const int tx = tid & 31, ty0 = tid >> 5;
        #pragma unroll
        for (int i = 0; i < 4; i++) {
            const int ty = ty0 + 8 * i;
            tile[ty][tx] = Wv[(size_t)(k0 + ty) * 512 + (n0 + tx)];
        }
        __syncthreads();
        #pragma unroll
        for (int i = 0; i < 4; i++) {
            const int ty = ty0 + 8 * i;
            g_WvT[(size_t)(n0 + ty) * DIN + (k0 + tx)] = __float2half(tile[tx][ty]);
        }
    } else if (b < 1552) {               // zero g_cnt
        g_cnt[(b - 1536) * 256 + tid] = 0;
    } else {                             // vecprep: bqWk, wqbk, bqbk
        const int gw = (b - 1552) * 8 + (tid >> 5);
        const int lane = tid & 31;
        const float* rowp; const float* vecp; float* outp;
        if (gw < DIN)            { rowp = Wk + (size_t)gw * 512;         vecp = bq; outp = g_bqWk + gw; }
        else if (gw < 2 * DIN)   { rowp = Wq + (size_t)(gw - DIN) * 512; vecp = bk; outp = g_wqbk + (gw - DIN); }
        else if (gw == 2 * DIN)  { rowp = bq;                            vecp = bk; outp = g_bqbk; }
        else return;
        const float4* r4 = (const float4*)rowp;
        const float4* v4 = (const float4*)vecp;
        float d = 0.f;
        #pragma unroll
        for (int it = 0; it < 4; it++) {
            float4 a = r4[lane + 32 * it], bb2 = v4[lane + 32 * it];
            d += a.x * bb2.x + a.y * bb2.y + a.z * bb2.z + a.w * bb2.w;
        }
        #pragma unroll
        for (int off = 16; off > 0; off >>= 1) d += __shfl_down_sync(0xFFFFFFFFu, d, off);
        if (lane == 0) *outp = d;
    }
}

// ---------------- fuseBC: G-GEMM | hist | X1 split (hi only) + c0 --------------
// grid = 64 + 128 + 4096 = 4288 blocks x 256, dyn smem GEMM_SMEM
__global__ __launch_bounds__(256, 2)
void fuseBC_kernel(const int* __restrict__ row_map, const float* __restrict__ X1)
{
    const int b = blockIdx.x, t = threadIdx.x;
    if (b < 64) {                        // Gt = Wk . Wq^T (M=1024,N=1024,K=512) -> fp16
        gemm_body<true>(b & 7, b >> 3, g_Wkh, g_Wkl, g_Wqf, g_zb,
                        nullptr, g_Gh, nullptr, DIN, 512);
        return;
    }
    if (b < 192) {                       // histogram
        atomicAdd(&g_cnt[row_map[(b - 64) * 256 + t]], 1);
        return;
    }
    __shared__ float sred[8];
    const int row = b - 192;
    const size_t i = (size_t)row * DIN + t * 4;
    float4 v = *(const float4*)(X1 + i);
    __half2 hp0 = {__float2half(v.x), __float2half(v.y)};
    __half2 hp1 = {__float2half(v.z), __float2half(v.w)};
    *(__half2*)(g_X1h + i)     = hp0;
    *(__half2*)(g_X1h + i + 2) = hp1;
    const float4 w = *(const float4*)(g_wqbk + t * 4);
    float d = v.x * w.x + v.y * w.y + v.z * w.z + v.w * w.w;
    #pragma unroll
    for (int off = 16; off > 0; off >>= 1) d += __shfl_down_sync(0xFFFFFFFFu, d, off);
    if ((t & 31) == 0) sred[t >> 5] = d;
    __syncthreads();
    if (t < 8) {
        float s = sred[t];
        #pragma unroll
        for (int off = 4; off > 0; off >>= 1) s += __shfl_down_sync(0xFFu, s, off);
        if (t == 0) g_c0[row] = s + g_bqbk[0];
    }
}

// ---------------- scan (256 threads, 16 elems/thread, 2 barriers) --------------
__device__ __forceinline__ void scan_body() {
    __shared__ int wsum[8];
    const int t = threadIdx.x;
    int v[16];
    #pragma unroll
    for (int q = 0; q < 4; q++) {
        int4 c = *(const int4*)&g_cnt[16 * t + 4 * q];
        v[4 * q] = c.x; v[4 * q + 1] = c.y; v[4 * q + 2] = c.z; v[4 * q + 3] = c.w;
    }
    int run = 0;
    #pragma unroll
    for (int i = 0; i < 16; i++) { const int tmp = v[i]; v[i] = run; run += tmp; }
    const int lane = t & 31, w = t >> 5;
    int incl = run;
    #pragma unroll
    for (int off = 1; off < 32; off <<= 1) {
        const int n = __shfl_up_sync(0xFFFFFFFFu, incl, off);
        if (lane >= off) incl += n;
    }
    if (lane == 31) wsum[w] = incl;
    const int lane_excl = incl - run;
    __syncthreads();
    if (t < 8) {
        const int o = wsum[t];
        int s = o;
        #pragma unroll
        for (int off = 1; off < 8; off <<= 1) {
            const int n = __shfl_up_sync(0xFFu, s, off);
            if (t >= off) s += n;
        }
        wsum[t] = s - o;     // exclusive warp offset
    }
    __syncthreads();
    const int base = wsum[w] + lane_excl;
    #pragma unroll
    for (int i = 0; i < 16; i++) {
        const int o = base + v[i];
        g_off[16 * t + i] = o;
        g_cur[16 * t + i] = o;
    }
    if (t == 255) g_off[NQ] = base + run;
}

// ---------------- fuseD: U-GEMM (single-term) | scan --------------------------
// grid = 256 + 1 blocks x 256, dyn smem GEMM_SMEM
__global__ __launch_bounds__(256, 2)
void fuseD_kernel()
{
    const int b = blockIdx.x;
    if (b < 256) {                       // U = X1h . G + bq.Wk^T (M=4096,N=1024,K=1024)
        gemm_body<false>(b & 7, b >> 3, g_X1h, nullptr, g_Gh, g_bqWk,
                         g_U, nullptr, nullptr, DIN, 1024);
        return;
    }
    scan_body();
}

// ---------------- C-GEMM: C = Y . Wv + bv, empty rows zeroed ------------------
__global__ __launch_bounds__(256, 2)
void cgemm_kernel(const float* __restrict__ bv, float* __restrict__ out)
{
    gemm_body<true>(blockIdx.x, blockIdx.y, g_Yh, g_Yl, g_WvT, bv,
                    out, nullptr, g_cnt, 512, 1024);
}

// ---------------- fill ----------------
__global__ void fill_kernel(const int* __restrict__ row_map) {
    const int j = blockIdx.x * 256 + threadIdx.x;
    if (j < NK) {
        const int pos = atomicAdd(&g_cur[row_map[j]], 1);
        g_idx[pos] = j;
    }
}

// ---------------- fused attention: scores + online softmax + Y (fp16 split) ----
#define CH 64
__global__ void attn_kernel(const float* __restrict__ X2) {
    __shared__ float ssc[CH];
    const int qi = blockIdx.x;
    const int s = g_off[qi], e = g_off[qi + 1];
    const int t = threadIdx.x, wid = t >> 5, lane = t & 31;
    const size_t yo = (size_t)qi * DIN + t * 4;
    if (e == s) {
        __half2 z = {__float2half(0.f), __float2half(0.f)};
        *(__half2*)(g_Yh + yo) = z; *(__half2*)(g_Yh + yo + 2) = z;
        *(__half2*)(g_Yl + yo) = z; *(__half2*)(g_Yl + yo + 2) = z;
        return;
    }
    const float c0 = g_c0[qi];
    const float4* u4 = (const float4*)(g_U + (size_t)qi * DIN);
    float m = -1e30f, den = 0.f;
    float4 acc = make_float4(0.f, 0.f, 0.f, 0.f);

    for (int t0 = s; t0 < e; t0 += CH) {
        const int nt = min(CH, e - t0);
        for (int tt = wid; tt < nt; tt += 8) {
            const int j = g_idx[t0 + tt];
            const float4* x4 = (const float4*)(X2 + (size_t)j * DIN);
            float d = 0.f;
            #pragma unroll
            for (int it = 0; it < 8; it++) {
                float4 a = x4[lane + 32 * it], b = u4[lane + 32 * it];
                d += a.x * b.x + a.y * b.y + a.z * b.z + a.w * b.w;
            }
            #pragma unroll
            for (int off = 16; off > 0; off >>= 1)
                d += __shfl_down_sync(0xFFFFFFFFu, d, off);
            if (lane == 0) ssc[tt] = (d + c0) * 0.044194173824159216f;
        }
        __syncthreads();
        float mc = -1e30f;
        for (int k = 0; k < nt; k++) mc = fmaxf(mc, ssc[k]);
        const float mnew = fmaxf(m, mc);
        const float resc = expf(m - mnew);
        den *= resc;
        acc.x *= resc; acc.y *= resc; acc.z *= resc; acc.w *= resc;
        for (int k = 0; k < nt; k++) {
            const int j = g_idx[t0 + k];
            const float w = expf(ssc[k] - mnew);
            den += w;
            const float4 v = *(const float4*)(X2 + (size_t)j * DIN + t * 4);
            acc.x += w * v.x; acc.y += w * v.y; acc.z += w * v.z; acc.w += w * v.w;
        }
        m = mnew;
        __syncthreads();
    }
    const float inv = 1.0f / den;
    const float y0 = acc.x * inv, y1 = acc.y * inv, y2 = acc.z * inv, y3 = acc.w * inv;
    __half h0 = __float2half(y0), h1 = __float2half(y1);
    __half h2 = __float2half(y2), h3 = __float2half(y3);
    __half2 hp0 = {h0, h1}, hp1 = {h2, h3};
    __half2 lp0 = {__float2half(y0 - __half2float(h0)), __float2half(y1 - __half2float(h1))};
    __half2 lp1 = {__float2half(y2 - __half2float(h2)), __float2half(y3 - __half2float(h3))};
    *(__half2*)(g_Yh + yo)     = hp0;
    *(__half2*)(g_Yh + yo + 2) = hp1;
    *(__half2*)(g_Yl + yo)     = lp0;
    *(__half2*)(g_Yl + yo + 2) = lp1;
}

// ---------------- launcher ----------------
extern "C" void kernel_launch(void* const* d_in, const int* in_sizes, int n_in,
                              void* d_out, int out_size)
{
    const float* X1 = (const float*)d_in[0];
    const float* X2 = (const float*)d_in[1];
    const float* Wq = (const float*)d_in[2];
    const float* bq = (const float*)d_in[3];
    const float* Wk = (const float*)d_in[4];
    const float* bk = (const float*)d_in[5];
    const float* Wv = (const float*)d_in[6];
    const float* bv = (const float*)d_in[7];
    const int*   row_map = (const int*)d_in[8];
    float* out = (float*)d_out;

    cudaFuncSetAttribute(fuseBC_kernel, cudaFuncAttributeMaxDynamicSharedMemorySize, GEMM_SMEM);
    cudaFuncSetAttribute(fuseD_kernel,  cudaFuncAttributeMaxDynamicSharedMemorySize, GEMM_SMEM);
    cudaFuncSetAttribute(cgemm_kernel,  cudaFuncAttributeMaxDynamicSharedMemorySize, GEMM_SMEM);

    // 1. independent prep + zero_cnt
    fuseA_kernel<<<1809, 256>>>(Wq, Wk, Wv, bq, bk);
    // 2. G-GEMM | hist | X1-split + c0
    fuseBC_kernel<<<4288, 256, GEMM_SMEM>>>(row_map, X1);
    // 3. U-GEMM (single-term) | scan
    fuseD_kernel<<<257, 256, GEMM_SMEM>>>();
    // 4. fill
    fill_kernel<<<NK / 256, 256>>>(row_map);
    // 5. fused attention -> Y (fp16 hi/lo)
    attn_kernel<<<NQ, 256>>>(X2);
    // 6. C = Y . Wv + bv, empty rows zeroed
    cgemm_kernel<<<dim3(4, 32), 256, GEMM_SMEM>>>(bv, out);
}

// round 12
// speedup vs baseline: 3.7687x; 1.0810x over previous
#include <cuda_runtime.h>
#include <cuda_fp16.h>
#include <math.h>
#include <stdint.h>

#define NQ 4096
#define NK 32768
#define DIN 1024
#define DQK 512
#define DV 512

// ---------------- scratch (no allocations allowed) ----------------
__device__ __half g_X1h[(size_t)NQ * DIN];
__device__ __half g_Yh[(size_t)NQ * DIN];
__device__ __half g_Wkh[(size_t)DIN * 512];   // Wk split hi   [d2][c]
__device__ __half g_Wkl[(size_t)DIN * 512];   // Wk split lo
__device__ __half g_Wqf[(size_t)DIN * 512];   // fl16(Wq)      [d1][c]
__device__ __half g_WvT[(size_t)512 * DIN];   // Wv^T [n][k] fp16
__device__ __half g_Gh[(size_t)DIN * DIN];    // Gt = Wk.Wq^T, fp16
__device__ float g_U[(size_t)NQ * DIN];       // U = X1.G + bq.Wk^T
__device__ float g_c0[NQ];                    // Q[i].bk
__device__ float g_bqWk[DIN];
__device__ float g_wqbk[DIN];
__device__ float g_bqbk[1];
__device__ float g_zb[DIN];                   // zero bias (never written)
__device__ int   g_cnt[NQ];
__device__ int   g_off[NQ + 1];
__device__ int   g_cur[NQ];
__device__ int   g_idx[NK];

// ---------------- PTX helpers (portable sm_80+) ----------------
__device__ __forceinline__ void cp16(uint32_t dst, const void* src) {
    asm volatile("cp.async.cg.shared.global [%0], [%1], 16;" :: "r"(dst), "l"(src));
}
__device__ __forceinline__ void cp_commit() {
    asm volatile("cp.async.commit_group;" ::: "memory");
}
template <int N> __device__ __forceinline__ void cp_wait() {
    asm volatile("cp.async.wait_group %0;" :: "n"(N) : "memory");
}
__device__ __forceinline__ void ldsm4(uint32_t* r, uint32_t addr) {
    asm volatile("ldmatrix.sync.aligned.m8n8.x4.shared.b16 {%0,%1,%2,%3}, [%4];"
                 : "=r"(r[0]), "=r"(r[1]), "=r"(r[2]), "=r"(r[3]) : "r"(addr));
}
__device__ __forceinline__ void mma16816(float* c, const uint32_t* a, const uint32_t* b) {
    asm volatile(
        "mma.sync.aligned.m16n8k16.row.col.f32.f16.f16.f32 "
        "{%0,%1,%2,%3}, {%4,%5,%6,%7}, {%8,%9}, {%0,%1,%2,%3};"
        : "+f"(c[0]), "+f"(c[1]), "+f"(c[2]), "+f"(c[3])
        : "r"(a[0]), "r"(a[1]), "r"(a[2]), "r"(a[3]), "r"(b[0]), "r"(b[1]));
}

#define TILE_B   8192
#define STAGE_B  (3 * TILE_B)
#define NSTAGE   4
#define GEMM_SMEM (NSTAGE * STAGE_B)   // 98304

// ---------------- GEMM body: C = (Ah [+ Al]) * B^T + bias ----------------
template <bool TWO>
__device__ __forceinline__ void gemm_body(
    int bx, int by,
    const __half* __restrict__ Ah, const __half* __restrict__ Al,
    const __half* __restrict__ B, const float* __restrict__ bias,
    float* __restrict__ Cf, __half* __restrict__ Ch,
    const int* __restrict__ cnt, int ldc, int kdim)
{
    extern __shared__ char smem[];
    const uint32_t sb = (uint32_t)__cvta_generic_to_shared(smem);
    const int tid = threadIdx.x, wid = tid >> 5, lane = tid & 31;
    const int warp_m = wid & 1, warp_n = wid >> 1;
    const int m_base = by * 128;
    const int n_base = bx * 128;

    float acc[4][4][4];
    #pragma unroll
    for (int i = 0; i < 4; i++)
        #pragma unroll
        for (int j = 0; j < 4; j++)
            #pragma unroll
            for (int k = 0; k < 4; k++) acc[i][j][k] = 0.0f;

    const int fr0 = tid >> 2, fc0 = tid & 3;
    const int fr1 = fr0 + 64;
    const uint32_t fd0 = (uint32_t)(fr0 * 64 + ((fc0 ^ ((fr0 >> 1) & 3)) << 4));
    const uint32_t fd1 = (uint32_t)(fr1 * 64 + ((fc0 ^ ((fr1 >> 1) & 3)) << 4));

    auto issue_loads = [&](int gi) {
        const int koff = gi * 32, s = gi & 3;
        const uint32_t st = sb + s * STAGE_B;
        const size_t aoff = (size_t)m_base * kdim + koff + fc0 * 8;
        const size_t boff = (size_t)n_base * kdim + koff + fc0 * 8;
        cp16(st + fd0,              Ah + aoff + (size_t)fr0 * kdim);
        cp16(st + fd1,              Ah + aoff + (size_t)fr1 * kdim);
        if (TWO) {
            cp16(st + TILE_B + fd0, Al + aoff + (size_t)fr0 * kdim);
            cp16(st + TILE_B + fd1, Al + aoff + (size_t)fr1 * kdim);
        }
        cp16(st + 2 * TILE_B + fd0, B + boff + (size_t)fr0 * kdim);
        cp16(st + 2 * TILE_B + fd1, B + boff + (size_t)fr1 * kdim);
        cp_commit();
    };

    issue_loads(0);
    issue_loads(1);
    issue_loads(2);

    const int a_row = warp_m * 64 + (lane & 15);
    const int a_half = lane >> 4;
    const int a_s = ((lane & 15) >> 1) & 3;
    const int b_row = warp_n * 32 + ((lane >> 4) << 3) + (lane & 7);
    const int b_half = (lane >> 3) & 1;
    const int b_s = ((lane & 7) >> 1) & 3;

    const int NSTEP = kdim / 32;
    for (int gi = 0; gi < NSTEP; gi++) {
        if (gi + 3 < NSTEP) cp_wait<2>(); else cp_wait<0>();
        __syncthreads();
        if (gi + 3 < NSTEP) issue_loads(gi + 3);

        const uint32_t st = sb + (gi & 3) * STAGE_B;
        const uint32_t sAh = st, sAl = st + TILE_B, sB = st + 2 * TILE_B;

        #pragma unroll
        for (int kh = 0; kh < 2; kh++) {
            const uint32_t acb = (uint32_t)(((kh * 2 + a_half) ^ a_s) << 4);
            const uint32_t bcb = (uint32_t)(((kh * 2 + b_half) ^ b_s) << 4);
            uint32_t bf[2][4], af[4][4];
            #pragma unroll
            for (int nf2 = 0; nf2 < 2; nf2++)
                ldsm4(bf[nf2], sB + (uint32_t)((b_row + nf2 * 16) * 64) + bcb);
            #pragma unroll
            for (int mf = 0; mf < 4; mf++)
                ldsm4(af[mf], sAh + (uint32_t)((a_row + mf * 16) * 64) + acb);
            #pragma unroll
            for (int mf = 0; mf < 4; mf++)
                #pragma unroll
                for (int nf = 0; nf < 4; nf++)
                    mma16816(acc[mf][nf], af[mf], &bf[nf >> 1][(nf & 1) * 2]);
            if (TWO) {
                #pragma unroll
                for (int mf = 0; mf < 4; mf++)
                    ldsm4(af[mf], sAl + (uint32_t)((a_row + mf * 16) * 64) + acb);
                #pragma unroll
                for (int mf = 0; mf < 4; mf++)
                    #pragma unroll
                    for (int nf = 0; nf < 4; nf++)
                        mma16816(acc[mf][nf], af[mf], &bf[nf >> 1][(nf & 1) * 2]);
            }
        }
    }

    const int col0 = n_base + warp_n * 32 + (lane & 3) * 2;
    const int r0   = m_base + warp_m * 64 + (lane >> 2);
    #pragma unroll
    for (int mf = 0; mf < 4; mf++) {
        const int ra = r0 + mf * 16, rb = ra + 8;
        const bool za = cnt && (cnt[ra] == 0);
        const bool zbm = cnt && (cnt[rb] == 0);
        #pragma unroll
        for (int nf = 0; nf < 4; nf++) {
            const int col = col0 + nf * 8;
            const float b0 = bias[col], b1 = bias[col + 1];
            float v0 = za ? 0.f : acc[mf][nf][0] + b0;
            float v1 = za ? 0.f : acc[mf][nf][1] + b1;
            float v2 = zbm ? 0.f : acc[mf][nf][2] + b0;
            float v3 = zbm ? 0.f : acc[mf][nf][3] + b1;
            if (Ch) {
                __half2 ha = {__float2half(v0), __float2half(v1)};
                __half2 hb = {__float2half(v2), __float2half(v3)};
                *(__half2*)(Ch + (size_t)ra * ldc + col) = ha;
                *(__half2*)(Ch + (size_t)rb * ldc + col) = hb;
            } else {
                *(float2*)(Cf + (size_t)ra * ldc + col) = make_float2(v0, v1);
                *(float2*)(Cf + (size_t)rb * ldc + col) = make_float2(v2, v3);
            }
        }
    }
}

// ---------------- fuseA: split-Wk | conv-Wq | wtrans-Wv | zero_cnt | vecprep ----
__global__ void fuseA_kernel(const float* __restrict__ Wq, const float* __restrict__ Wk,
                             const float* __restrict__ Wv, const float* __restrict__ bq,
                             const float* __restrict__ bk)
{
    const int b = blockIdx.x, tid = threadIdx.x;
    if (b < 512) {                       // Wk fp32 -> hi/lo split
        const size_t i = 4 * ((size_t)b * 256 + tid);
        float4 v = *(const float4*)(Wk + i);
        __half h0 = __float2half(v.x), h1 = __float2half(v.y);
        __half h2 = __float2half(v.z), h3 = __float2half(v.w);
        __half2 hp0 = {h0, h1}, hp1 = {h2, h3};
        __half2 lp0 = {__float2half(v.x - __half2float(h0)), __float2half(v.y - __half2float(h1))};
        __half2 lp1 = {__float2half(v.z - __half2float(h2)), __float2half(v.w - __half2float(h3))};
        *(__half2*)(g_Wkh + i)     = hp0;
        *(__half2*)(g_Wkh + i + 2) = hp1;
        *(__half2*)(g_Wkl + i)     = lp0;
        *(__half2*)(g_Wkl + i + 2) = lp1;
    } else if (b < 1024) {               // Wq fp32 -> fp16
        const size_t i = 4 * ((size_t)(b - 512) * 256 + tid);
        float4 v = *(const float4*)(Wq + i);
        __half2 p0 = {__float2half(v.x), __float2half(v.y)};
        __half2 p1 = {__float2half(v.z), __float2half(v.w)};
        *(__half2*)(g_Wqf + i)     = p0;
        *(__half2*)(g_Wqf + i + 2) = p1;
    } else if (b < 1536) {               // Wv[k][n] -> WvT[n][k] fp16
        __shared__ float tile[32][33];
        const int bb = b - 1024;
        const int n0 = (bb & 15) * 32, k0 = (bb >> 4) * 32;
        const int tx = tid & 31, ty0 = tid >> 5;
        #pragma unroll
        for (int i = 0; i < 4; i++) {
            const int ty = ty0 + 8 * i;
            tile[ty][tx] = Wv[(size_t)(k0 + ty) * 512 + (n0 + tx)];
        }
        __syncthreads();
        #pragma unroll
        for (int i = 0; i < 4; i++) {
            const int ty = ty0 + 8 * i;
            g_WvT[(size_t)(n0 + ty) * DIN + (k0 + tx)] = __float2half(tile[tx][ty]);
        }
    } else if (b < 1552) {               // zero g_cnt
        g_cnt[(b - 1536) * 256 + tid] = 0;
    } else {                             // vecprep: bqWk, wqbk, bqbk
        const int gw = (b - 1552) * 8 + (tid >> 5);
        const int lane = tid & 31;
        const float* rowp; const float* vecp; float* outp;
        if (gw < DIN)            { rowp = Wk + (size_t)gw * 512;         vecp = bq; outp = g_bqWk + gw; }
        else if (gw < 2 * DIN)   { rowp = Wq + (size_t)(gw - DIN) * 512; vecp = bk; outp = g_wqbk + (gw - DIN); }
        else if (gw == 2 * DIN)  { rowp = bq;                            vecp = bk; outp = g_bqbk; }
        else return;
        const float4* r4 = (const float4*)rowp;
        const float4* v4 = (const float4*)vecp;
        float d = 0.f;
        #pragma unroll
        for (int it = 0; it < 4; it++) {
            float4 a = r4[lane + 32 * it], bb2 = v4[lane + 32 * it];
            d += a.x * bb2.x + a.y * bb2.y + a.z * bb2.z + a.w * bb2.w;
        }
        #pragma unroll
        for (int off = 16; off > 0; off >>= 1) d += __shfl_down_sync(0xFFFFFFFFu, d, off);
        if (lane == 0) *outp = d;
    }
}

// ---------------- fuseBC: G-GEMM | hist | X1 split (hi only) + c0 --------------
__global__ __launch_bounds__(256, 2)
void fuseBC_kernel(const int* __restrict__ row_map, const float* __restrict__ X1)
{
    const int b = blockIdx.x, t = threadIdx.x;
    if (b < 64) {                        // Gt = Wk . Wq^T (M=1024,N=1024,K=512) -> fp16
        gemm_body<true>(b & 7, b >> 3, g_Wkh, g_Wkl, g_Wqf, g_zb,
                        nullptr, g_Gh, nullptr, DIN, 512);
        return;
    }
    if (b < 192) {                       // histogram
        atomicAdd(&g_cnt[row_map[(b - 64) * 256 + t]], 1);
        return;
    }
    __shared__ float sred[8];
    const int row = b - 192;
    const size_t i = (size_t)row * DIN + t * 4;
    float4 v = *(const float4*)(X1 + i);
    __half2 hp0 = {__float2half(v.x), __float2half(v.y)};
    __half2 hp1 = {__float2half(v.z), __float2half(v.w)};
    *(__half2*)(g_X1h + i)     = hp0;
    *(__half2*)(g_X1h + i + 2) = hp1;
    const float4 w = *(const float4*)(g_wqbk + t * 4);
    float d = v.x * w.x + v.y * w.y + v.z * w.z + v.w * w.w;
    #pragma unroll
    for (int off = 16; off > 0; off >>= 1) d += __shfl_down_sync(0xFFFFFFFFu, d, off);
    if ((t & 31) == 0) sred[t >> 5] = d;
    __syncthreads();
    if (t < 8) {
        float s = sred[t];
        #pragma unroll
        for (int off = 4; off > 0; off >>= 1) s += __shfl_down_sync(0xFFu, s, off);
        if (t == 0) g_c0[row] = s + g_bqbk[0];
    }
}

// ---------------- scan: 1 block, 256 threads, 16 elems/thread ----------------
__global__ void scan_kernel() {
    __shared__ int wsum[8];
    const int t = threadIdx.x;
    int v[16];
    #pragma unroll
    for (int q = 0; q < 4; q++) {
        int4 c = *(const int4*)&g_cnt[16 * t + 4 * q];
        v[4 * q] = c.x; v[4 * q + 1] = c.y; v[4 * q + 2] = c.z; v[4 * q + 3] = c.w;
    }
    int run = 0;
    #pragma unroll
    for (int i = 0; i < 16; i++) { const int tmp = v[i]; v[i] = run; run += tmp; }
    const int lane = t & 31, w = t >> 5;
    int incl = run;
    #pragma unroll
    for (int off = 1; off < 32; off <<= 1) {
        const int n = __shfl_up_sync(0xFFFFFFFFu, incl, off);
        if (lane >= off) incl += n;
    }
    if (lane == 31) wsum[w] = incl;
    const int lane_excl = incl - run;
    __syncthreads();
    if (t < 8) {
        const int o = wsum[t];
        int s = o;
        #pragma unroll
        for (int off = 1; off < 8; off <<= 1) {
            const int n = __shfl_up_sync(0xFFu, s, off);
            if (t >= off) s += n;
        }
        wsum[t] = s - o;
    }
    __syncthreads();
    const int base = wsum[w] + lane_excl;
    #pragma unroll
    for (int i = 0; i < 16; i++) {
        const int o = base + v[i];
        g_off[16 * t + i] = o;
        g_cur[16 * t + i] = o;
    }
    if (t == 255) g_off[NQ] = base + run;
}

// ---------------- fuseD: U-GEMM (single-term) | fill --------------------------
// grid = 256 + 128 blocks x 256, dyn smem GEMM_SMEM
__global__ __launch_bounds__(256, 2)
void fuseD_kernel(const int* __restrict__ row_map)
{
    const int b = blockIdx.x;
    if (b < 256) {                       // U = X1h . G + bq.Wk^T (M=4096,N=1024,K=1024)
        gemm_body<false>(b & 7, b >> 3, g_X1h, nullptr, g_Gh, g_bqWk,
                         g_U, nullptr, nullptr, DIN, 1024);
        return;
    }
    const int j = (b - 256) * 256 + threadIdx.x;
    const int pos = atomicAdd(&g_cur[row_map[j]], 1);
    g_idx[pos] = j;
}

// ---------------- C-GEMM: C = Yh . Wv + bv (single-term), empty rows zeroed ----
__global__ __launch_bounds__(256, 2)
void cgemm_kernel(const float* __restrict__ bv, float* __restrict__ out)
{
    gemm_body<false>(blockIdx.x, blockIdx.y, g_Yh, nullptr, g_WvT, bv,
                     out, nullptr, g_cnt, 512, 1024);
}

// ---------------- fused attention: scores + online softmax + Y (fp16) ----------
#define CH 64
__global__ void attn_kernel(const float* __restrict__ X2) {
    __shared__ float ssc[CH];
    const int qi = blockIdx.x;
    const int s = g_off[qi], e = g_off[qi + 1];
    const int t = threadIdx.x, wid = t >> 5, lane = t & 31;
    const size_t yo = (size_t)qi * DIN + t * 4;
    if (e == s) {
        __half2 z = {__float2half(0.f), __float2half(0.f)};
        *(__half2*)(g_Yh + yo) = z; *(__half2*)(g_Yh + yo + 2) = z;
        return;
    }
    const float c0 = g_c0[qi];
    const float4* u4 = (const float4*)(g_U + (size_t)qi * DIN);
    float m = -1e30f, den = 0.f;
    float4 acc = make_float4(0.f, 0.f, 0.f, 0.f);

    for (int t0 = s; t0 < e; t0 += CH) {
        const int nt = min(CH, e - t0);
        for (int tt = wid; tt < nt; tt += 8) {
            const int j = g_idx[t0 + tt];
            const float4* x4 = (const float4*)(X2 + (size_t)j * DIN);
            float d = 0.f;
            #pragma unroll
            for (int it = 0; it < 8; it++) {
                float4 a = x4[lane + 32 * it], b = u4[lane + 32 * it];
                d += a.x * b.x + a.y * b.y + a.z * b.z + a.w * b.w;
            }
            #pragma unroll
            for (int off = 16; off > 0; off >>= 1)
                d += __shfl_down_sync(0xFFFFFFFFu, d, off);
            if (lane == 0) ssc[tt] = (d + c0) * 0.044194173824159216f;
        }
        __syncthreads();
        float mc = -1e30f;
        for (int k = 0; k < nt; k++) mc = fmaxf(mc, ssc[k]);
        const float mnew = fmaxf(m, mc);
        const float resc = expf(m - mnew);
        den *= resc;
        acc.x *= resc; acc.y *= resc; acc.z *= resc; acc.w *= resc;
        for (int k = 0; k < nt; k++) {
            const int j = g_idx[t0 + k];
            const float w = expf(ssc[k] - mnew);
            den += w;
            const float4 v = *(const float4*)(X2 + (size_t)j * DIN + t * 4);
            acc.x += w * v.x; acc.y += w * v.y; acc.z += w * v.z; acc.w += w * v.w;
        }
        m = mnew;
        __syncthreads();
    }
    const float inv = 1.0f / den;
    __half2 hp0 = {__float2half(acc.x * inv), __float2half(acc.y * inv)};
    __half2 hp1 = {__float2half(acc.z * inv), __float2half(acc.w * inv)};
    *(__half2*)(g_Yh + yo)     = hp0;
    *(__half2*)(g_Yh + yo + 2) = hp1;
}

// ---------------- launcher ----------------
extern "C" void kernel_launch(void* const* d_in, const int* in_sizes, int n_in,
                              void* d_out, int out_size)
{
    const float* X1 = (const float*)d_in[0];
    const float* X2 = (const float*)d_in[1];
    const float* Wq = (const float*)d_in[2];
    const float* bq = (const float*)d_in[3];
    const float* Wk = (const float*)d_in[4];
    const float* bk = (const float*)d_in[5];
    const float* Wv = (const float*)d_in[6];
    const float* bv = (const float*)d_in[7];
    const int*   row_map = (const int*)d_in[8];
    float* out = (float*)d_out;

    cudaFuncSetAttribute(fuseBC_kernel, cudaFuncAttributeMaxDynamicSharedMemorySize, GEMM_SMEM);
    cudaFuncSetAttribute(fuseD_kernel,  cudaFuncAttributeMaxDynamicSharedMemorySize, GEMM_SMEM);
    cudaFuncSetAttribute(cgemm_kernel,  cudaFuncAttributeMaxDynamicSharedMemorySize, GEMM_SMEM);

    // 1. independent prep + zero_cnt
    fuseA_kernel<<<1809, 256>>>(Wq, Wk, Wv, bq, bk);
    // 2. G-GEMM | hist | X1-split + c0
    fuseBC_kernel<<<4288, 256, GEMM_SMEM>>>(row_map, X1);
    // 3. scan (tiny)
    scan_kernel<<<1, 256>>>();
    // 4. U-GEMM (single-term) | fill
    fuseD_kernel<<<384, 256, GEMM_SMEM>>>(row_map);
    // 5. fused attention -> Yh (fp16)
    attn_kernel<<<NQ, 256>>>(X2);
    // 6. C = Yh . Wv + bv (single-term), empty rows zeroed
    cgemm_kernel<<<dim3(4, 32), 256, GEMM_SMEM>>>(bv, out);
}